// round 9
// baseline (speedup 1.0000x reference)
#include <cuda_runtime.h>
#include <float.h>
#include <math.h>

// ---------------------------------------------------------------------------
// Problem constants
// ---------------------------------------------------------------------------
#define BB    8
#define NN    2048
#define KNNK  20
#define CIN   67          // 3 xyz + 64 feat
#define CFE   64
#define CCC   144         // 64 gpn + 64 center + 16 pos
#define CR    80          // reduced per-k channels: 64 grouped + 16 pos
#define CH    64
#define DIMV  16
#define DIMK  32
#define NHEAD 8
#define COUT  128
#define EPSF  1e-5f
#define XYZ_TOT (BB*NN*3)

typedef unsigned long long ull;

// scratch (no allocation allowed -> __device__ globals)
__device__ int    g_idx[BB * NN * KNNK];
__device__ float4 W1gp[(CR/4) * CH];            // [c4 0..19][o]
__device__ float4 W1dp[(CFE/4) * CH];           // [c4 0..15][o]  W1[:,64:128]-W1[:,:64]
__device__ float4 W2p [(CH/4)  * CH];           // [c4][o]
__device__ float4 Wqp [(CH/4)  * (NHEAD*DIMK)]; // [c4][o]
__device__ float4 Wvgp[(CR/4) * DIMV];          // [c4 0..19][vd]
__device__ float4 Wvdp[(CFE/4) * DIMV];         // [c4 0..15][vd]
__device__ float4 Wkgp[(CR/4) * DIMK];          // [c4 0..19][d]

// ---------------------------------------------------------------------------
// packed dual-fp32 FMA helpers
// ---------------------------------------------------------------------------
__device__ __forceinline__ void ffma2(ull& d, ull a, ull b)
{
    asm("fma.rn.f32x2 %0, %1, %2, %0;" : "+l"(d) : "l"(a), "l"(b));
}
__device__ __forceinline__ float hsum2(ull v)
{
    float lo, hi;
    asm("mov.b64 {%0, %1}, %2;" : "=f"(lo), "=f"(hi) : "l"(v));
    return lo + hi;
}
__device__ __forceinline__ ulonglong2 ldp(const void* p)
{
    return *(const ulonglong2*)p;
}

// ---------------------------------------------------------------------------
// Kernel 0: pack weights (transposed + center-folded layouts)
// ---------------------------------------------------------------------------
__global__ void pack_weights(const float* __restrict__ W1, const float* __restrict__ W2,
                             const float* __restrict__ Wq, const float* __restrict__ Wv,
                             const float* __restrict__ Wk)
{
    int i = blockIdx.x * blockDim.x + threadIdx.x;

    if (i < (CR/4)*CH) {
        int c4 = i >> 6, o = i & 63;
        int col = (c4 < 16) ? 4 * c4 : 128 + 4 * (c4 - 16);
        W1gp[i] = *(const float4*)&W1[o * CCC + col];
        return;
    }
    i -= (CR/4)*CH;
    if (i < (CFE/4)*CH) {
        int c4 = i >> 6, o = i & 63;
        float4 a = *(const float4*)&W1[o * CCC + 64 + 4 * c4];
        float4 b = *(const float4*)&W1[o * CCC + 4 * c4];
        W1dp[i] = make_float4(a.x - b.x, a.y - b.y, a.z - b.z, a.w - b.w);
        return;
    }
    i -= (CFE/4)*CH;
    if (i < (CH/4)*CH) {
        int c4 = i >> 6, o = i & 63;
        W2p[i] = *(const float4*)&W2[o * CH + 4 * c4];
        return;
    }
    i -= (CH/4)*CH;
    if (i < (CH/4)*NHEAD*DIMK) {
        int c4 = i >> 8, o = i & 255;
        Wqp[i] = *(const float4*)&Wq[o * CH + 4 * c4];
        return;
    }
    i -= (CH/4)*NHEAD*DIMK;
    if (i < (CR/4)*DIMV) {
        int c4 = i >> 4, vd = i & 15;
        int col = (c4 < 16) ? 4 * c4 : 128 + 4 * (c4 - 16);
        Wvgp[i] = *(const float4*)&Wv[vd * CCC + col];
        return;
    }
    i -= (CR/4)*DIMV;
    if (i < (CFE/4)*DIMV) {
        int c4 = i >> 4, vd = i & 15;
        float4 a = *(const float4*)&Wv[vd * CCC + 64 + 4 * c4];
        float4 b = *(const float4*)&Wv[vd * CCC + 4 * c4];
        Wvdp[i] = make_float4(a.x - b.x, a.y - b.y, a.z - b.z, a.w - b.w);
        return;
    }
    i -= (CFE/4)*DIMV;
    if (i < (CR/4)*DIMK) {
        int c4 = i >> 5, d = i & 31;
        int col = (c4 < 16) ? 4 * c4 : 128 + 4 * (c4 - 16);
        Wkgp[i] = *(const float4*)&Wk[d * CCC + col];
    }
}

// ---------------------------------------------------------------------------
// Kernel 1: brute-force KNN with cached-local-argmin selection
// ---------------------------------------------------------------------------
__global__ void knn_kernel(const float* __restrict__ x)
{
    extern __shared__ float sm[];
    float* sx   = sm;
    float* sy   = sx + NN;
    float* sz   = sy + NN;
    float* ss   = sz + NN;
    float* dist = ss + NN;      // [8][NN]

    const int b     = blockIdx.x >> 8;
    const int qbase = (blockIdx.x & 255) << 3;
    const int t     = threadIdx.x;
    const int w     = t >> 5;
    const int lane  = t & 31;

    for (int j = t; j < NN; j += 256) {
        const float* p = x + ((size_t)b * NN + j) * CIN;
        float a0 = p[0], a1 = p[1], a2 = p[2];
        sx[j] = a0; sy[j] = a1; sz[j] = a2;
        ss[j] = a0 * a0 + a1 * a1 + a2 * a2;
    }
    __syncthreads();

    const int n = qbase + w;
    const float qx = sx[n], qy = sy[n], qz = sz[n], sq = ss[n];
    float* dw = dist + w * NN;

    for (int j = lane; j < NN; j += 32) {
        float dot = qx * sx[j] + qy * sy[j] + qz * sz[j];
        dw[j] = -2.0f * dot + sq + ss[j];
    }
    __syncwarp();

    float bv = FLT_MAX;
    int   bi = 0x7fffffff;
    #pragma unroll 8
    for (int j = lane; j < NN; j += 32) {
        float v = dw[j];
        if (v < bv) { bv = v; bi = j; }
    }

    for (int sel = 0; sel < KNNK; sel++) {
        float wv = bv;
        int   wi = bi;
        #pragma unroll
        for (int o = 16; o; o >>= 1) {
            float ov = __shfl_xor_sync(0xffffffffu, wv, o);
            int   oi = __shfl_xor_sync(0xffffffffu, wi, o);
            if (ov < wv || (ov == wv && oi < wi)) { wv = ov; wi = oi; }
        }
        if (lane == 0)
            g_idx[((size_t)b * NN + n) * KNNK + sel] = wi;
        if (bi == wi) {
            dw[wi] = FLT_MAX;
            bv = FLT_MAX; bi = 0x7fffffff;
            #pragma unroll 8
            for (int j = lane; j < NN; j += 32) {
                float v = dw[j];
                if (v < bv) { bv = v; bi = j; }
            }
        }
    }
}

// ---------------------------------------------------------------------------
// block reduce helper (256 threads)
// ---------------------------------------------------------------------------
__device__ __forceinline__ float block_sum_256(float v, float* sred, float* sbc)
{
    #pragma unroll
    for (int o = 16; o; o >>= 1) v += __shfl_xor_sync(0xffffffffu, v, o);
    if ((threadIdx.x & 31) == 0) sred[threadIdx.x >> 5] = v;
    __syncthreads();
    if (threadIdx.x == 0) {
        float s = 0.f;
        #pragma unroll
        for (int i = 0; i < 8; i++) s += sred[i];
        *sbc = s;
    }
    __syncthreads();
    return *sbc;
}

// ---------------------------------------------------------------------------
// Kernel 2: fused per-point block. One block (256 thr) per (b, n).
// ---------------------------------------------------------------------------
__global__ void __launch_bounds__(256, 3)
fused_kernel(const float* __restrict__ x,
             const float* __restrict__ Wh,
             const float* __restrict__ g1, const float* __restrict__ b1,
             const float* __restrict__ g2, const float* __restrict__ b2,
             const float* __restrict__ lnqw, const float* __restrict__ lnqb,
             const float* __restrict__ lnvw, const float* __restrict__ lnvb,
             const float* __restrict__ lnow, const float* __restrict__ lnob,
             float* __restrict__ out)
{
    const int bn = blockIdx.x;
    const int b  = bn >> 11;
    const int n  = bn & (NN - 1);
    const int t  = threadIdx.x;

    __shared__ __align__(16) float sF [KNNK * CR];      // 20 x 80
    __shared__ __align__(16) float sH1[KNNK * CH];      // 20 x 64
    __shared__ __align__(16) float sPM[4 * CH];         // partial max per kg
    __shared__ __align__(16) float sFQ[CH];
    __shared__ __align__(16) float sQ [NHEAD * DIMK];   // 256
    __shared__ __align__(16) float sV [KNNK * DIMV];    // 320
    __shared__ __align__(16) float sKK[KNNK * DIMK];    // 640
    __shared__ __align__(16) float sKV[DIMK * DIMV];    // 512
    __shared__ __align__(16) float sCF[CFE];
    __shared__ __align__(16) float sC1[CH];
    __shared__ __align__(16) float sCV[DIMV];
    __shared__ int   sIdx[KNNK];
    __shared__ float sred[8];
    __shared__ float sbc[1];

    const float* xb = x + (size_t)b * NN * CIN;
    const float* xc = xb + (size_t)n * CIN;

    if (t < CFE)  sCF[t]  = xc[3 + t];
    if (t < KNNK) sIdx[t] = g_idx[(size_t)bn * KNNK + t];
    __syncthreads();

    // ---- per-point constant vectors (center-folded) --------------------------
    if (t < CH + DIMV) {
        ull a = 0ull;
        if (t < CH) {
            #pragma unroll
            for (int c4 = 0; c4 < CFE / 4; c4++) {
                const ulonglong2 w = ldp(&W1dp[c4 * CH + t]);
                const ulonglong2 f = ldp(&sCF[4 * c4]);
                ffma2(a, w.x, f.x);
                ffma2(a, w.y, f.y);
            }
            sC1[t] = hsum2(a);
        } else {
            const int vd = t - CH;
            #pragma unroll
            for (int c4 = 0; c4 < CFE / 4; c4++) {
                const ulonglong2 w = ldp(&Wvdp[c4 * DIMV + vd]);
                const ulonglong2 f = ldp(&sCF[4 * c4]);
                ffma2(a, w.x, f.x);
                ffma2(a, w.y, f.y);
            }
            sCV[vd] = hsum2(a);
        }
    }

    // ---- build F = [grouped | pos] -------------------------------------------
    for (int i = t; i < KNNK * CFE; i += 256) {
        const int k = i >> 6, c = i & 63;
        const float* np = xb + (size_t)sIdx[k] * CIN;
        sF[k * CR + c] = np[3 + c];
    }
    {
        const float cx = xc[0], cy = xc[1], cz = xc[2];
        for (int i = t; i < KNNK * DIMV; i += 256) {
            const int k = i >> 4, vd = i & 15;
            const float* np = xb + (size_t)sIdx[k] * CIN;
            const float rx = np[0] - cx, ry = np[1] - cy, rz = np[2] - cz;
            sF[k * CR + CFE + vd] =
                Wh[vd * 3 + 0] * rx + Wh[vd * 3 + 1] * ry + Wh[vd * 3 + 2] * rz;
        }
    }
    __syncthreads();

    const float bn_rs = rsqrtf(1.0f + EPSF);

    // ---- GEMM1: h1 = relu(bn1(W1g@Fk + c1)). o = t&63, kg = t>>6, 5 k each ----
    {
        const int o  = t & 63;
        const int kg = t >> 6;
        ull acc[5];
        #pragma unroll
        for (int j = 0; j < 5; j++) acc[j] = 0ull;
        #pragma unroll 5
        for (int c4 = 0; c4 < CR / 4; c4++) {
            const ulonglong2 w = ldp(&W1gp[c4 * CH + o]);
            #pragma unroll
            for (int j = 0; j < 5; j++) {
                const ulonglong2 f = ldp(&sF[(kg + 4 * j) * CR + 4 * c4]);
                ffma2(acc[j], w.x, f.x);
                ffma2(acc[j], w.y, f.y);
            }
        }
        const float c1 = sC1[o];
        const float sc = g1[o] * bn_rs;
        const float bo = b1[o];
        #pragma unroll
        for (int j = 0; j < 5; j++)
            sH1[(kg + 4 * j) * CH + o] = fmaxf((hsum2(acc[j]) + c1) * sc + bo, 0.f);
    }
    __syncthreads();

    // ---- GEMM2 + partial max (h2 only feeds max_k) -----------------------------
    {
        const int o  = t & 63;
        const int kg = t >> 6;
        ull acc[5];
        #pragma unroll
        for (int j = 0; j < 5; j++) acc[j] = 0ull;
        #pragma unroll 4
        for (int c4 = 0; c4 < CH / 4; c4++) {
            const ulonglong2 w = ldp(&W2p[c4 * CH + o]);
            #pragma unroll
            for (int j = 0; j < 5; j++) {
                const ulonglong2 f = ldp(&sH1[(kg + 4 * j) * CH + 4 * c4]);
                ffma2(acc[j], w.x, f.x);
                ffma2(acc[j], w.y, f.y);
            }
        }
        const float sc = g2[o] * bn_rs;
        const float bo = b2[o];
        float pm = 0.f;   // relu floor; max of relu'ed values >= 0
        #pragma unroll
        for (int j = 0; j < 5; j++)
            pm = fmaxf(pm, hsum2(acc[j]) * sc + bo);
        sPM[kg * CH + o] = pm;
    }
    __syncthreads();

    if (t < CH)
        sFQ[t] = fmaxf(fmaxf(sPM[t], sPM[CH + t]),
                       fmaxf(sPM[2 * CH + t], sPM[3 * CH + t]));
    __syncthreads();

    // ---- q = relu(LN_256(W_q @ fq)); one output per thread ----------------------
    {
        ull a = 0ull;
        #pragma unroll
        for (int c4 = 0; c4 < CH / 4; c4++) {
            const ulonglong2 w = ldp(&Wqp[c4 * 256 + t]);
            const ulonglong2 f = ldp(&sFQ[4 * c4]);
            ffma2(a, w.x, f.x);
            ffma2(a, w.y, f.y);
        }
        const float qv   = hsum2(a);
        const float s    = block_sum_256(qv, sred, sbc);
        const float mean = s * (1.f / 256.f);
        const float d0   = qv - mean;
        const float vs   = block_sum_256(d0 * d0, sred, sbc);
        const float inv  = rsqrtf(vs * (1.f / 256.f) + EPSF);
        sQ[t] = fmaxf((qv - mean) * inv * lnqw[t] + lnqb[t], 0.f);
    }

    // ---- v-raw: vd = t&15, kq = t>>4 (k = kq, +16 if kq<4) -----------------------
    {
        const int vd = t & 15;
        const int kq = t >> 4;
        ull a0 = 0ull, a1 = 0ull;
        const bool has2 = (kq < 4);
        #pragma unroll 5
        for (int c4 = 0; c4 < CR / 4; c4++) {
            const ulonglong2 w  = ldp(&Wvgp[c4 * DIMV + vd]);
            const ulonglong2 f0 = ldp(&sF[kq * CR + 4 * c4]);
            ffma2(a0, w.x, f0.x);  ffma2(a0, w.y, f0.y);
            if (has2) {
                const ulonglong2 f1 = ldp(&sF[(kq + 16) * CR + 4 * c4]);
                ffma2(a1, w.x, f1.x);  ffma2(a1, w.y, f1.y);
            }
        }
        const float cv = sCV[vd];
        sV[kq * DIMV + vd] = hsum2(a0) + cv;
        if (has2) sV[(kq + 16) * DIMV + vd] = hsum2(a1) + cv;
    }

    // ---- kk-raw: d = t&31, kb = t>>5 (k = kb, kb+8, +16 if kb<4) ------------------
    {
        const int d  = t & 31;
        const int kb = t >> 5;
        ull a0 = 0ull, a1 = 0ull, a2 = 0ull;
        const bool has2 = (kb < 4);
        #pragma unroll 5
        for (int c4 = 0; c4 < CR / 4; c4++) {
            const ulonglong2 w  = ldp(&Wkgp[c4 * DIMK + d]);
            const ulonglong2 f0 = ldp(&sF[kb * CR + 4 * c4]);
            const ulonglong2 f1 = ldp(&sF[(kb + 8) * CR + 4 * c4]);
            ffma2(a0, w.x, f0.x);  ffma2(a0, w.y, f0.y);
            ffma2(a1, w.x, f1.x);  ffma2(a1, w.y, f1.y);
            if (has2) {
                const ulonglong2 f2 = ldp(&sF[(kb + 16) * CR + 4 * c4]);
                ffma2(a2, w.x, f2.x);  ffma2(a2, w.y, f2.y);
            }
        }
        sKK[kb * DIMK + d]       = hsum2(a0);
        sKK[(kb + 8) * DIMK + d] = hsum2(a1);
        if (has2) sKK[(kb + 16) * DIMK + d] = hsum2(a2);
    }
    __syncthreads();

    // ---- LN_16 over v (threads 0-19) and softmax over k (threads 128-159) --------
    if (t < KNNK) {
        float m = 0.f;
        #pragma unroll
        for (int vd = 0; vd < DIMV; vd++) m += sV[t * DIMV + vd];
        m *= (1.f / DIMV);
        float var = 0.f;
        #pragma unroll
        for (int vd = 0; vd < DIMV; vd++) {
            const float d = sV[t * DIMV + vd] - m;
            var += d * d;
        }
        var *= (1.f / DIMV);
        const float inv = rsqrtf(var + EPSF);
        #pragma unroll
        for (int vd = 0; vd < DIMV; vd++)
            sV[t * DIMV + vd] = (sV[t * DIMV + vd] - m) * inv * lnvw[vd] + lnvb[vd];
    } else if (t >= 128 && t < 128 + DIMK) {
        const int d = t - 128;
        float mx = -FLT_MAX;
        #pragma unroll
        for (int k = 0; k < KNNK; k++) mx = fmaxf(mx, sKK[k * DIMK + d]);
        float sum = 0.f;
        #pragma unroll
        for (int k = 0; k < KNNK; k++) {
            const float e = expf(sKK[k * DIMK + d] - mx);
            sKK[k * DIMK + d] = e;
            sum += e;
        }
        const float inv = 1.f / sum;
        #pragma unroll
        for (int k = 0; k < KNNK; k++) sKK[k * DIMK + d] *= inv;
    }
    __syncthreads();

    // ---- kv[d][v] = sum_k kk[k][d] * v[k][v] ---------------------------------------
    for (int i = t; i < DIMK * DIMV; i += 256) {
        const int d = i >> 4, vd = i & 15;
        float acc = 0.f;
        #pragma unroll
        for (int k = 0; k < KNNK; k++)
            acc += sKK[k * DIMK + d] * sV[k * DIMV + vd];
        sKV[i] = acc;
    }
    __syncthreads();

    // ---- out = LN_128(q @ kv), write transposed --------------------------------------
    {
        float acc = 0.f;
        if (t < COUT) {
            const int h = t >> 4, vd = t & 15;
            #pragma unroll
            for (int d = 0; d < DIMK; d++)
                acc += sQ[h * DIMK + d] * sKV[d * DIMV + vd];
        }
        const float s    = block_sum_256(t < COUT ? acc : 0.f, sred, sbc);
        const float mean = s * (1.f / COUT);
        const float dd   = (t < COUT) ? (acc - mean) : 0.f;
        const float vs   = block_sum_256(dd * dd, sred, sbc);
        if (t < COUT) {
            const float inv = rsqrtf(vs * (1.f / COUT) + EPSF);
            const float ov  = (acc - mean) * inv * lnow[t] + lnob[t];
            out[XYZ_TOT + ((size_t)b * COUT + t) * NN + n] = ov;
        }
    }
    if (t < 3)
        out[(size_t)bn * 3 + t] = xc[t];
}

// ---------------------------------------------------------------------------
// launch
// ---------------------------------------------------------------------------
extern "C" void kernel_launch(void* const* d_in, const int* in_sizes, int n_in,
                              void* d_out, int out_size)
{
    const float* x    = (const float*)d_in[0];
    const float* Wh   = (const float*)d_in[1];
    const float* W1   = (const float*)d_in[2];
    const float* g1   = (const float*)d_in[3];
    const float* b1   = (const float*)d_in[4];
    const float* W2   = (const float*)d_in[5];
    const float* g2   = (const float*)d_in[6];
    const float* b2   = (const float*)d_in[7];
    const float* Wq   = (const float*)d_in[8];
    const float* lnqw = (const float*)d_in[9];
    const float* lnqb = (const float*)d_in[10];
    const float* Wv   = (const float*)d_in[11];
    const float* lnvw = (const float*)d_in[12];
    const float* lnvb = (const float*)d_in[13];
    const float* Wk   = (const float*)d_in[14];
    const float* lnow = (const float*)d_in[15];
    const float* lnob = (const float*)d_in[16];
    float* out = (float*)d_out;

    const int pack_total = (CR/4)*CH + (CFE/4)*CH + (CH/4)*CH + (CH/4)*NHEAD*DIMK
                         + (CR/4)*DIMV + (CFE/4)*DIMV + (CR/4)*DIMK;
    pack_weights<<<(pack_total + 127) / 128, 128>>>(W1, W2, Wq, Wv, Wk);

    const int knn_smem = (4 * NN + 8 * NN) * (int)sizeof(float);  // 96 KB
    cudaFuncSetAttribute(knn_kernel,
                         cudaFuncAttributeMaxDynamicSharedMemorySize, knn_smem);
    knn_kernel<<<BB * (NN / 8), 256, knn_smem>>>(x);

    fused_kernel<<<BB * NN, 256>>>(x, Wh,
                                   g1, b1, g2, b2,
                                   lnqw, lnqb, lnvw, lnvb,
                                   lnow, lnob,
                                   out);
}

// round 10
// speedup vs baseline: 1.2760x; 1.2760x over previous
#include <cuda_runtime.h>
#include <float.h>
#include <math.h>

// ---------------------------------------------------------------------------
// Problem constants
// ---------------------------------------------------------------------------
#define BB    8
#define NN    2048
#define KNNK  20
#define CIN   67          // 3 xyz + 64 feat
#define CFE   64
#define CCC   144         // 64 gpn + 64 center + 16 pos
#define CR    80          // reduced per-k channels: 64 grouped + 16 pos
#define CH    64
#define DIMV  16
#define DIMK  32
#define NHEAD 8
#define COUT  128
#define EPSF  1e-5f
#define XYZ_TOT (BB*NN*3)

typedef unsigned long long ull;

// scratch (no allocation allowed -> __device__ globals)
__device__ int    g_idx[BB * NN * KNNK];
__device__ float4 W1gp[(CR/4) * CH];            // [c4 0..19][o]
__device__ float4 W1dp[(CFE/4) * CH];           // [c4 0..15][o]  W1[:,64:128]-W1[:,:64]
__device__ float4 W2p [(CH/4)  * CH];           // [c4][o]
__device__ float4 Wqp [(CH/4)  * (NHEAD*DIMK)]; // [c4][o]
__device__ float4 Wvgp[(CR/4) * DIMV];          // [c4 0..19][vd]
__device__ float4 Wvdp[(CFE/4) * DIMV];         // [c4 0..15][vd]
__device__ float4 Wkgp[(CR/4) * DIMK];          // [c4 0..19][d]

// ---------------------------------------------------------------------------
// packed dual-fp32 FMA helpers
// ---------------------------------------------------------------------------
__device__ __forceinline__ void ffma2(ull& d, ull a, ull b)
{
    asm("fma.rn.f32x2 %0, %1, %2, %0;" : "+l"(d) : "l"(a), "l"(b));
}
__device__ __forceinline__ float hsum2(ull v)
{
    float lo, hi;
    asm("mov.b64 {%0, %1}, %2;" : "=f"(lo), "=f"(hi) : "l"(v));
    return lo + hi;
}
__device__ __forceinline__ ulonglong2 ldp(const void* p)
{
    return *(const ulonglong2*)p;
}

// ---------------------------------------------------------------------------
// Kernel 0: pack weights (transposed + center-folded layouts)
// ---------------------------------------------------------------------------
__global__ void pack_weights(const float* __restrict__ W1, const float* __restrict__ W2,
                             const float* __restrict__ Wq, const float* __restrict__ Wv,
                             const float* __restrict__ Wk)
{
    int i = blockIdx.x * blockDim.x + threadIdx.x;

    if (i < (CR/4)*CH) {
        int c4 = i >> 6, o = i & 63;
        int col = (c4 < 16) ? 4 * c4 : 128 + 4 * (c4 - 16);
        W1gp[i] = *(const float4*)&W1[o * CCC + col];
        return;
    }
    i -= (CR/4)*CH;
    if (i < (CFE/4)*CH) {
        int c4 = i >> 6, o = i & 63;
        float4 a = *(const float4*)&W1[o * CCC + 64 + 4 * c4];
        float4 b = *(const float4*)&W1[o * CCC + 4 * c4];
        W1dp[i] = make_float4(a.x - b.x, a.y - b.y, a.z - b.z, a.w - b.w);
        return;
    }
    i -= (CFE/4)*CH;
    if (i < (CH/4)*CH) {
        int c4 = i >> 6, o = i & 63;
        W2p[i] = *(const float4*)&W2[o * CH + 4 * c4];
        return;
    }
    i -= (CH/4)*CH;
    if (i < (CH/4)*NHEAD*DIMK) {
        int c4 = i >> 8, o = i & 255;
        Wqp[i] = *(const float4*)&Wq[o * CH + 4 * c4];
        return;
    }
    i -= (CH/4)*NHEAD*DIMK;
    if (i < (CR/4)*DIMV) {
        int c4 = i >> 4, vd = i & 15;
        int col = (c4 < 16) ? 4 * c4 : 128 + 4 * (c4 - 16);
        Wvgp[i] = *(const float4*)&Wv[vd * CCC + col];
        return;
    }
    i -= (CR/4)*DIMV;
    if (i < (CFE/4)*DIMV) {
        int c4 = i >> 4, vd = i & 15;
        float4 a = *(const float4*)&Wv[vd * CCC + 64 + 4 * c4];
        float4 b = *(const float4*)&Wv[vd * CCC + 4 * c4];
        Wvdp[i] = make_float4(a.x - b.x, a.y - b.y, a.z - b.z, a.w - b.w);
        return;
    }
    i -= (CFE/4)*DIMV;
    if (i < (CR/4)*DIMK) {
        int c4 = i >> 5, d = i & 31;
        int col = (c4 < 16) ? 4 * c4 : 128 + 4 * (c4 - 16);
        Wkgp[i] = *(const float4*)&Wk[d * CCC + col];
    }
}

// ---------------------------------------------------------------------------
// Kernel 1: brute-force KNN; per-lane top-2 cache, rare rescans
// ---------------------------------------------------------------------------
__global__ void knn_kernel(const float* __restrict__ x)
{
    extern __shared__ float sm[];
    float* sx   = sm;
    float* sy   = sx + NN;
    float* sz   = sy + NN;
    float* ss   = sz + NN;
    float* dist = ss + NN;      // [8][NN]

    const int b     = blockIdx.x >> 8;
    const int qbase = (blockIdx.x & 255) << 3;
    const int t     = threadIdx.x;
    const int w     = t >> 5;
    const int lane  = t & 31;

    for (int j = t; j < NN; j += 256) {
        const float* p = x + ((size_t)b * NN + j) * CIN;
        float a0 = p[0], a1 = p[1], a2 = p[2];
        sx[j] = a0; sy[j] = a1; sz[j] = a2;
        ss[j] = a0 * a0 + a1 * a1 + a2 * a2;
    }
    __syncthreads();

    const int n = qbase + w;
    const float qx = sx[n], qy = sy[n], qz = sz[n], sq = ss[n];
    float* dw = dist + w * NN;

    // distance write + per-lane top-2 in one pass
    float v1 = FLT_MAX, v2 = FLT_MAX;
    int   i1 = 0x7fffffff, i2 = 0x7fffffff;
    for (int j = lane; j < NN; j += 32) {
        const float dot = qx * sx[j] + qy * sy[j] + qz * sz[j];
        const float d   = -2.0f * dot + sq + ss[j];
        dw[j] = d;
        if (d < v1)      { v2 = v1; i2 = i1; v1 = d; i1 = j; }
        else if (d < v2) { v2 = d;  i2 = j; }
    }
    __syncwarp();

    for (int sel = 0; sel < KNNK; sel++) {
        float wv = v1;
        int   wi = i1;
        #pragma unroll
        for (int o = 16; o; o >>= 1) {
            float ov = __shfl_xor_sync(0xffffffffu, wv, o);
            int   oi = __shfl_xor_sync(0xffffffffu, wi, o);
            if (ov < wv || (ov == wv && oi < wi)) { wv = ov; wi = oi; }
        }
        if (lane == 0)
            g_idx[((size_t)b * NN + n) * KNNK + sel] = wi;
        if (i1 == wi) {                 // owner lane
            dw[wi] = FLT_MAX;           // mark consumed
            v1 = v2; i1 = i2;           // promote cached runner-up
            v2 = FLT_MAX; i2 = 0x7fffffff;
            if (v1 == FLT_MAX) {        // cache exhausted -> rescan stripe
                for (int j = lane; j < NN; j += 32) {
                    const float d = dw[j];
                    if (d < v1)      { v2 = v1; i2 = i1; v1 = d; i1 = j; }
                    else if (d < v2) { v2 = d;  i2 = j; }
                }
            }
        }
        __syncwarp();
    }
}

// ---------------------------------------------------------------------------
// fused block reduction: sum of (a, b) over 128 threads
// ---------------------------------------------------------------------------
__device__ __forceinline__ float2 block_sum2_128(float a, float b,
                                                 float2* sred, float2* sbc)
{
    #pragma unroll
    for (int o = 16; o; o >>= 1) {
        a += __shfl_xor_sync(0xffffffffu, a, o);
        b += __shfl_xor_sync(0xffffffffu, b, o);
    }
    if ((threadIdx.x & 31) == 0) sred[threadIdx.x >> 5] = make_float2(a, b);
    __syncthreads();
    if (threadIdx.x == 0) {
        float2 s0 = sred[0], s1 = sred[1], s2 = sred[2], s3 = sred[3];
        *sbc = make_float2(s0.x + s1.x + s2.x + s3.x,
                           s0.y + s1.y + s2.y + s3.y);
    }
    __syncthreads();
    return *sbc;
}

// ---------------------------------------------------------------------------
// Kernel 2: fused per-point block. One block (128 thr) per (b, n).
// ---------------------------------------------------------------------------
__global__ void __launch_bounds__(128, 4)
fused_kernel(const float* __restrict__ x,
             const float* __restrict__ Wh,
             const float* __restrict__ g1, const float* __restrict__ b1,
             const float* __restrict__ g2, const float* __restrict__ b2,
             const float* __restrict__ lnqw, const float* __restrict__ lnqb,
             const float* __restrict__ lnvw, const float* __restrict__ lnvb,
             const float* __restrict__ lnow, const float* __restrict__ lnob,
             float* __restrict__ out)
{
    const int bn = blockIdx.x;
    const int b  = bn >> 11;
    const int n  = bn & (NN - 1);
    const int t  = threadIdx.x;

    __shared__ __align__(16) float sF [KNNK * CR];      // 20 x 80
    __shared__ __align__(16) float sH1[KNNK * CH];      // 20 x 64
    __shared__ __align__(16) float sPM[2 * CH];         // GEMM2 partial max
    __shared__ __align__(16) float sFQ[CH];
    __shared__ __align__(16) float sQ [NHEAD * DIMK];   // 256
    __shared__ __align__(16) float sV [KNNK * DIMV];    // 320
    __shared__ __align__(16) float sKK[KNNK * DIMK];    // 640
    __shared__ __align__(16) float sKV[DIMK * DIMV];    // 512
    __shared__ __align__(16) float sCF[CFE];
    __shared__ __align__(16) float sC1[CH];
    __shared__ __align__(16) float sCV[DIMV];
    __shared__ int    sIdx[KNNK];
    __shared__ float2 sred[4];
    __shared__ float2 sbc[1];

    const float* xb = x + (size_t)b * NN * CIN;
    const float* xc = xb + (size_t)n * CIN;
    const float cx = xc[0], cy = xc[1], cz = xc[2];

    if (t < CFE)  sCF[t]  = xc[3 + t];
    if (t < KNNK) sIdx[t] = g_idx[(size_t)bn * KNNK + t];
    __syncthreads();

    // ---- per-point constant vectors (center-folded) --------------------------
    if (t < CH + DIMV) {
        ull a = 0ull;
        if (t < CH) {
            #pragma unroll
            for (int c4 = 0; c4 < CFE / 4; c4++) {
                const ulonglong2 w = ldp(&W1dp[c4 * CH + t]);
                const ulonglong2 f = ldp(&sCF[4 * c4]);
                ffma2(a, w.x, f.x);
                ffma2(a, w.y, f.y);
            }
            sC1[t] = hsum2(a);
        } else {
            const int vd = t - CH;
            #pragma unroll
            for (int c4 = 0; c4 < CFE / 4; c4++) {
                const ulonglong2 w = ldp(&Wvdp[c4 * DIMV + vd]);
                const ulonglong2 f = ldp(&sCF[4 * c4]);
                ffma2(a, w.x, f.x);
                ffma2(a, w.y, f.y);
            }
            sCV[vd] = hsum2(a);
        }
    }

    // ---- build F = [grouped | pos] -------------------------------------------
    for (int i = t; i < KNNK * CFE; i += 128) {
        const int k = i >> 6, c = i & 63;
        const float* np = xb + (size_t)sIdx[k] * CIN;
        sF[k * CR + c] = np[3 + c];
    }
    for (int i = t; i < KNNK * DIMV; i += 128) {
        const int k = i >> 4, vd = i & 15;
        const float* np = xb + (size_t)sIdx[k] * CIN;
        const float rx = np[0] - cx, ry = np[1] - cy, rz = np[2] - cz;
        sF[k * CR + CFE + vd] =
            Wh[vd * 3 + 0] * rx + Wh[vd * 3 + 1] * ry + Wh[vd * 3 + 2] * rz;
    }
    __syncthreads();

    const float bn_rs = rsqrtf(1.0f + EPSF);

    // ---- GEMM1: h1 = relu(bn1(W1g@Fk + c1)). o = t&63, kg = t>>6, 10 k each ---
    {
        const int o  = t & 63;
        const int kg = t >> 6;
        ull acc[10];
        #pragma unroll
        for (int j = 0; j < 10; j++) acc[j] = 0ull;
        for (int c4 = 0; c4 < CR / 4; c4++) {
            const ulonglong2 w = ldp(&W1gp[c4 * CH + o]);
            #pragma unroll
            for (int j = 0; j < 10; j++) {
                const ulonglong2 f = ldp(&sF[(kg + 2 * j) * CR + 4 * c4]);
                ffma2(acc[j], w.x, f.x);
                ffma2(acc[j], w.y, f.y);
            }
        }
        const float c1 = sC1[o];
        const float sc = g1[o] * bn_rs;
        const float bo = b1[o];
        #pragma unroll
        for (int j = 0; j < 10; j++)
            sH1[(kg + 2 * j) * CH + o] = fmaxf((hsum2(acc[j]) + c1) * sc + bo, 0.f);
    }
    __syncthreads();

    // ---- GEMM2 + fold relu/max over k into epilogue ----------------------------
    {
        const int o  = t & 63;
        const int kg = t >> 6;
        ull acc[10];
        #pragma unroll
        for (int j = 0; j < 10; j++) acc[j] = 0ull;
        for (int c4 = 0; c4 < CH / 4; c4++) {
            const ulonglong2 w = ldp(&W2p[c4 * CH + o]);
            #pragma unroll
            for (int j = 0; j < 10; j++) {
                const ulonglong2 f = ldp(&sH1[(kg + 2 * j) * CH + 4 * c4]);
                ffma2(acc[j], w.x, f.x);
                ffma2(acc[j], w.y, f.y);
            }
        }
        const float sc = g2[o] * bn_rs;
        const float bo = b2[o];
        float pm = 0.f;           // relu floor
        #pragma unroll
        for (int j = 0; j < 10; j++)
            pm = fmaxf(pm, hsum2(acc[j]) * sc + bo);
        sPM[kg * CH + o] = pm;
    }
    __syncthreads();

    if (t < CH)
        sFQ[t] = fmaxf(sPM[t], sPM[CH + t]);
    __syncthreads();

    // ---- q = relu(LN_256(W_q @ fq)); fused sum/sumsq reduction ------------------
    {
        float qv[2];
        #pragma unroll
        for (int r = 0; r < 2; r++) {
            const int o = t + r * 128;
            ull a = 0ull;
            #pragma unroll
            for (int c4 = 0; c4 < CH / 4; c4++) {
                const ulonglong2 w = ldp(&Wqp[c4 * 256 + o]);
                const ulonglong2 f = ldp(&sFQ[4 * c4]);
                ffma2(a, w.x, f.x);
                ffma2(a, w.y, f.y);
            }
            qv[r] = hsum2(a);
        }
        const float2 ssq  = block_sum2_128(qv[0] + qv[1],
                                           qv[0] * qv[0] + qv[1] * qv[1],
                                           sred, sbc);
        const float mean = ssq.x * (1.f / 256.f);
        const float var  = ssq.y * (1.f / 256.f) - mean * mean;
        const float inv  = rsqrtf(var + EPSF);
        #pragma unroll
        for (int r = 0; r < 2; r++) {
            const int o = t + r * 128;
            sQ[o] = fmaxf((qv[r] - mean) * inv * lnqw[o] + lnqb[o], 0.f);
        }
    }

    // ---- v-raw: vd = t&15, k0 = t>>4 (k = k0, k0+8, +16 if k0<4) ----------------
    {
        const int vd = t & 15;
        const int k0 = t >> 4;
        ull a0 = 0ull, a1 = 0ull, a2 = 0ull;
        const bool has2 = (k0 < 4);
        for (int c4 = 0; c4 < CR / 4; c4++) {
            const ulonglong2 w  = ldp(&Wvgp[c4 * DIMV + vd]);
            const ulonglong2 f0 = ldp(&sF[k0 * CR + 4 * c4]);
            const ulonglong2 f1 = ldp(&sF[(k0 + 8) * CR + 4 * c4]);
            ffma2(a0, w.x, f0.x);  ffma2(a0, w.y, f0.y);
            ffma2(a1, w.x, f1.x);  ffma2(a1, w.y, f1.y);
            if (has2) {
                const ulonglong2 f2 = ldp(&sF[(k0 + 16) * CR + 4 * c4]);
                ffma2(a2, w.x, f2.x);  ffma2(a2, w.y, f2.y);
            }
        }
        const float cv = sCV[vd];
        sV[k0 * DIMV + vd]       = hsum2(a0) + cv;
        sV[(k0 + 8) * DIMV + vd] = hsum2(a1) + cv;
        if (has2) sV[(k0 + 16) * DIMV + vd] = hsum2(a2) + cv;
    }

    // ---- kk-raw: d = t&31, kb = t>>5, 5 k each (no barrier since prev phase) ----
    {
        const int d  = t & 31;
        const int kb = t >> 5;
        ull a[5];
        #pragma unroll
        for (int p = 0; p < 5; p++) a[p] = 0ull;
        for (int c4 = 0; c4 < CR / 4; c4++) {
            const ulonglong2 w = ldp(&Wkgp[c4 * DIMK + d]);
            #pragma unroll
            for (int p = 0; p < 5; p++) {
                const ulonglong2 f = ldp(&sF[(kb + 4 * p) * CR + 4 * c4]);
                ffma2(a[p], w.x, f.x);
                ffma2(a[p], w.y, f.y);
            }
        }
        #pragma unroll
        for (int p = 0; p < 5; p++)
            sKK[(kb + 4 * p) * DIMK + d] = hsum2(a[p]);
    }
    __syncthreads();

    // ---- LN_16 over v (warp 0) || softmax over k (warp 2) -----------------------
    if (t < KNNK) {
        float s = 0.f, s2 = 0.f;
        #pragma unroll
        for (int vd = 0; vd < DIMV; vd++) {
            const float v = sV[t * DIMV + vd];
            s += v; s2 += v * v;
        }
        const float m   = s * (1.f / DIMV);
        const float var = s2 * (1.f / DIMV) - m * m;
        const float inv = rsqrtf(var + EPSF);
        #pragma unroll
        for (int vd = 0; vd < DIMV; vd++)
            sV[t * DIMV + vd] = (sV[t * DIMV + vd] - m) * inv * lnvw[vd] + lnvb[vd];
    } else if (t >= 64 && t < 64 + DIMK) {
        const int d = t - 64;
        float mx = -FLT_MAX;
        #pragma unroll
        for (int k = 0; k < KNNK; k++) mx = fmaxf(mx, sKK[k * DIMK + d]);
        float sum = 0.f;
        #pragma unroll
        for (int k = 0; k < KNNK; k++) {
            const float e = expf(sKK[k * DIMK + d] - mx);
            sKK[k * DIMK + d] = e;
            sum += e;
        }
        const float inv = 1.f / sum;
        #pragma unroll
        for (int k = 0; k < KNNK; k++) sKK[k * DIMK + d] *= inv;
    }
    __syncthreads();

    // ---- kv[d][v] = sum_k kk[k][d] * v[k][v] -------------------------------------
    for (int i = t; i < DIMK * DIMV; i += 128) {
        const int d = i >> 4, vd = i & 15;
        float acc = 0.f;
        #pragma unroll
        for (int k = 0; k < KNNK; k++)
            acc += sKK[k * DIMK + d] * sV[k * DIMV + vd];
        sKV[i] = acc;
    }
    __syncthreads();

    // ---- out = LN_128(q @ kv), fused stats, write transposed -----------------------
    {
        const int h = t >> 4, vd = t & 15;
        float acc = 0.f;
        #pragma unroll
        for (int d = 0; d < DIMK; d++)
            acc += sQ[h * DIMK + d] * sKV[d * DIMV + vd];

        const float2 ssq  = block_sum2_128(acc, acc * acc, sred, sbc);
        const float mean = ssq.x * (1.f / COUT);
        const float var  = ssq.y * (1.f / COUT) - mean * mean;
        const float inv  = rsqrtf(var + EPSF);
        const float ov   = (acc - mean) * inv * lnow[t] + lnob[t];

        out[XYZ_TOT + ((size_t)b * COUT + t) * NN + n] = ov;
    }
    if (t < 3) {
        const float v = (t == 0) ? cx : ((t == 1) ? cy : cz);
        out[(size_t)bn * 3 + t] = v;
    }
}

// ---------------------------------------------------------------------------
// launch
// ---------------------------------------------------------------------------
extern "C" void kernel_launch(void* const* d_in, const int* in_sizes, int n_in,
                              void* d_out, int out_size)
{
    const float* x    = (const float*)d_in[0];
    const float* Wh   = (const float*)d_in[1];
    const float* W1   = (const float*)d_in[2];
    const float* g1   = (const float*)d_in[3];
    const float* b1   = (const float*)d_in[4];
    const float* W2   = (const float*)d_in[5];
    const float* g2   = (const float*)d_in[6];
    const float* b2   = (const float*)d_in[7];
    const float* Wq   = (const float*)d_in[8];
    const float* lnqw = (const float*)d_in[9];
    const float* lnqb = (const float*)d_in[10];
    const float* Wv   = (const float*)d_in[11];
    const float* lnvw = (const float*)d_in[12];
    const float* lnvb = (const float*)d_in[13];
    const float* Wk   = (const float*)d_in[14];
    const float* lnow = (const float*)d_in[15];
    const float* lnob = (const float*)d_in[16];
    float* out = (float*)d_out;

    const int pack_total = (CR/4)*CH + (CFE/4)*CH + (CH/4)*CH + (CH/4)*NHEAD*DIMK
                         + (CR/4)*DIMV + (CFE/4)*DIMV + (CR/4)*DIMK;
    pack_weights<<<(pack_total + 127) / 128, 128>>>(W1, W2, Wq, Wv, Wk);

    const int knn_smem = (4 * NN + 8 * NN) * (int)sizeof(float);  // 96 KB
    cudaFuncSetAttribute(knn_kernel,
                         cudaFuncAttributeMaxDynamicSharedMemorySize, knn_smem);
    knn_kernel<<<BB * (NN / 8), 256, knn_smem>>>(x);

    fused_kernel<<<BB * NN, 128>>>(x, Wh,
                                   g1, b1, g2, b2,
                                   lnqw, lnqb, lnvw, lnvb,
                                   lnow, lnob,
                                   out);
}

// round 11
// speedup vs baseline: 1.2836x; 1.0059x over previous
#include <cuda_runtime.h>
#include <float.h>
#include <math.h>

// ---------------------------------------------------------------------------
// Problem constants
// ---------------------------------------------------------------------------
#define BB    8
#define NN    2048
#define KNNK  20
#define CIN   67          // 3 xyz + 64 feat
#define CFE   64
#define CCC   144         // 64 gpn + 64 center + 16 pos
#define CR    80          // reduced per-k channels: 64 grouped + 16 pos
#define CH    64
#define DIMV  16
#define DIMK  32
#define NHEAD 8
#define COUT  128
#define EPSF  1e-5f
#define XYZ_TOT (BB*NN*3)

typedef unsigned long long ull;

// scratch (no allocation allowed -> __device__ globals)
__device__ int    g_idx[BB * NN * KNNK];
__device__ float4 W1gp[(CR/4) * CH];            // [c4 0..19][o]
__device__ float4 W1dp[(CFE/4) * CH];           // [c4 0..15][o]  W1[:,64:128]-W1[:,:64]
__device__ float4 W2p [(CH/4)  * CH];           // [c4][o]
__device__ float4 Wqp [(CH/4)  * (NHEAD*DIMK)]; // [c4][o]
__device__ float4 Wvgp[(CR/4) * DIMV];          // [c4 0..19][vd]
__device__ float4 Wvdp[(CFE/4) * DIMV];         // [c4 0..15][vd]
__device__ float4 Wkgp[(CR/4) * DIMK];          // [c4 0..19][d]

// ---------------------------------------------------------------------------
// packed dual-fp32 FMA helpers
// ---------------------------------------------------------------------------
__device__ __forceinline__ void ffma2(ull& d, ull a, ull b)
{
    asm("fma.rn.f32x2 %0, %1, %2, %0;" : "+l"(d) : "l"(a), "l"(b));
}
__device__ __forceinline__ float hsum2(ull v)
{
    float lo, hi;
    asm("mov.b64 {%0, %1}, %2;" : "=f"(lo), "=f"(hi) : "l"(v));
    return lo + hi;
}
__device__ __forceinline__ ulonglong2 ldp(const void* p)
{
    return *(const ulonglong2*)p;
}

// ---------------------------------------------------------------------------
// Kernel 0: pack weights (transposed + center-folded layouts)
// ---------------------------------------------------------------------------
__global__ void pack_weights(const float* __restrict__ W1, const float* __restrict__ W2,
                             const float* __restrict__ Wq, const float* __restrict__ Wv,
                             const float* __restrict__ Wk)
{
    int i = blockIdx.x * blockDim.x + threadIdx.x;

    if (i < (CR/4)*CH) {
        int c4 = i >> 6, o = i & 63;
        int col = (c4 < 16) ? 4 * c4 : 128 + 4 * (c4 - 16);
        W1gp[i] = *(const float4*)&W1[o * CCC + col];
        return;
    }
    i -= (CR/4)*CH;
    if (i < (CFE/4)*CH) {
        int c4 = i >> 6, o = i & 63;
        float4 a = *(const float4*)&W1[o * CCC + 64 + 4 * c4];
        float4 b = *(const float4*)&W1[o * CCC + 4 * c4];
        W1dp[i] = make_float4(a.x - b.x, a.y - b.y, a.z - b.z, a.w - b.w);
        return;
    }
    i -= (CFE/4)*CH;
    if (i < (CH/4)*CH) {
        int c4 = i >> 6, o = i & 63;
        W2p[i] = *(const float4*)&W2[o * CH + 4 * c4];
        return;
    }
    i -= (CH/4)*CH;
    if (i < (CH/4)*NHEAD*DIMK) {
        int c4 = i >> 8, o = i & 255;
        Wqp[i] = *(const float4*)&Wq[o * CH + 4 * c4];
        return;
    }
    i -= (CH/4)*NHEAD*DIMK;
    if (i < (CR/4)*DIMV) {
        int c4 = i >> 4, vd = i & 15;
        int col = (c4 < 16) ? 4 * c4 : 128 + 4 * (c4 - 16);
        Wvgp[i] = *(const float4*)&Wv[vd * CCC + col];
        return;
    }
    i -= (CR/4)*DIMV;
    if (i < (CFE/4)*DIMV) {
        int c4 = i >> 4, vd = i & 15;
        float4 a = *(const float4*)&Wv[vd * CCC + 64 + 4 * c4];
        float4 b = *(const float4*)&Wv[vd * CCC + 4 * c4];
        Wvdp[i] = make_float4(a.x - b.x, a.y - b.y, a.z - b.z, a.w - b.w);
        return;
    }
    i -= (CFE/4)*DIMV;
    if (i < (CR/4)*DIMK) {
        int c4 = i >> 5, d = i & 31;
        int col = (c4 < 16) ? 4 * c4 : 128 + 4 * (c4 - 16);
        Wkgp[i] = *(const float4*)&Wk[d * CCC + col];
    }
}

// ---------------------------------------------------------------------------
// Kernel 1: brute-force KNN; per-lane top-2 cache, rare rescans
// ---------------------------------------------------------------------------
__global__ void knn_kernel(const float* __restrict__ x)
{
    extern __shared__ float sm[];
    float* sx   = sm;
    float* sy   = sx + NN;
    float* sz   = sy + NN;
    float* ss   = sz + NN;
    float* dist = ss + NN;      // [8][NN]

    const int b     = blockIdx.x >> 8;
    const int qbase = (blockIdx.x & 255) << 3;
    const int t     = threadIdx.x;
    const int w     = t >> 5;
    const int lane  = t & 31;

    for (int j = t; j < NN; j += 256) {
        const float* p = x + ((size_t)b * NN + j) * CIN;
        float a0 = p[0], a1 = p[1], a2 = p[2];
        sx[j] = a0; sy[j] = a1; sz[j] = a2;
        ss[j] = a0 * a0 + a1 * a1 + a2 * a2;
    }
    __syncthreads();

    const int n = qbase + w;
    const float qx = sx[n], qy = sy[n], qz = sz[n], sq = ss[n];
    float* dw = dist + w * NN;

    float v1 = FLT_MAX, v2 = FLT_MAX;
    int   i1 = 0x7fffffff, i2 = 0x7fffffff;
    for (int j = lane; j < NN; j += 32) {
        const float dot = qx * sx[j] + qy * sy[j] + qz * sz[j];
        const float d   = -2.0f * dot + sq + ss[j];
        dw[j] = d;
        if (d < v1)      { v2 = v1; i2 = i1; v1 = d; i1 = j; }
        else if (d < v2) { v2 = d;  i2 = j; }
    }
    __syncwarp();

    for (int sel = 0; sel < KNNK; sel++) {
        float wv = v1;
        int   wi = i1;
        #pragma unroll
        for (int o = 16; o; o >>= 1) {
            float ov = __shfl_xor_sync(0xffffffffu, wv, o);
            int   oi = __shfl_xor_sync(0xffffffffu, wi, o);
            if (ov < wv || (ov == wv && oi < wi)) { wv = ov; wi = oi; }
        }
        if (lane == 0)
            g_idx[((size_t)b * NN + n) * KNNK + sel] = wi;
        if (i1 == wi) {
            dw[wi] = FLT_MAX;
            v1 = v2; i1 = i2;
            v2 = FLT_MAX; i2 = 0x7fffffff;
            if (v1 == FLT_MAX) {
                for (int j = lane; j < NN; j += 32) {
                    const float d = dw[j];
                    if (d < v1)      { v2 = v1; i2 = i1; v1 = d; i1 = j; }
                    else if (d < v2) { v2 = d;  i2 = j; }
                }
            }
        }
        __syncwarp();
    }
}

// ---------------------------------------------------------------------------
// fused block reduction: sum of (a, b) over 128 threads
// ---------------------------------------------------------------------------
__device__ __forceinline__ float2 block_sum2_128(float a, float b,
                                                 float2* sred, float2* sbc)
{
    #pragma unroll
    for (int o = 16; o; o >>= 1) {
        a += __shfl_xor_sync(0xffffffffu, a, o);
        b += __shfl_xor_sync(0xffffffffu, b, o);
    }
    if ((threadIdx.x & 31) == 0) sred[threadIdx.x >> 5] = make_float2(a, b);
    __syncthreads();
    if (threadIdx.x == 0) {
        float2 s0 = sred[0], s1 = sred[1], s2 = sred[2], s3 = sred[3];
        *sbc = make_float2(s0.x + s1.x + s2.x + s3.x,
                           s0.y + s1.y + s2.y + s3.y);
    }
    __syncthreads();
    return *sbc;
}

// ---------------------------------------------------------------------------
// Kernel 2: fused per-point block. One block (128 thr) per (b, n).
// ---------------------------------------------------------------------------
__global__ void __launch_bounds__(128, 4)
fused_kernel(const float* __restrict__ x,
             const float* __restrict__ Wh,
             const float* __restrict__ g1, const float* __restrict__ b1,
             const float* __restrict__ g2, const float* __restrict__ b2,
             const float* __restrict__ lnqw, const float* __restrict__ lnqb,
             const float* __restrict__ lnvw, const float* __restrict__ lnvb,
             const float* __restrict__ lnow, const float* __restrict__ lnob,
             float* __restrict__ out)
{
    const int bn = blockIdx.x;
    const int b  = bn >> 11;
    const int n  = bn & (NN - 1);
    const int t  = threadIdx.x;

    __shared__ __align__(16) float sF [KNNK * CR];      // 20 x 80
    __shared__ __align__(16) float sH1[KNNK * CH];      // 20 x 64
    __shared__ __align__(16) float sPM[2 * CH];
    __shared__ __align__(16) float sFQ[CH];
    __shared__ __align__(16) float sQ [NHEAD * DIMK];
    __shared__ __align__(16) float sV [KNNK * DIMV];
    __shared__ __align__(16) float sKK[KNNK * DIMK];
    __shared__ __align__(16) float sKV[DIMK * DIMV];
    __shared__ __align__(16) float sCF[CFE];
    __shared__ __align__(16) float sC1[CH];
    __shared__ __align__(16) float sCV[DIMV];
    __shared__ int    sIdx[KNNK];
    __shared__ float2 sred[4];
    __shared__ float2 sbc[1];

    const float* xb = x + (size_t)b * NN * CIN;
    const float* xc = xb + (size_t)n * CIN;
    const float cx = xc[0], cy = xc[1], cz = xc[2];

    // off critical path
    if (t < 3)
        out[(size_t)bn * 3 + t] = xc[t];

    if (t < CFE)  sCF[t]  = xc[3 + t];
    if (t < KNNK) sIdx[t] = g_idx[(size_t)bn * KNNK + t];
    __syncthreads();

    // ---- per-point constant vectors (center-folded) --------------------------
    if (t < CH + DIMV) {
        ull a = 0ull;
        if (t < CH) {
            #pragma unroll
            for (int c4 = 0; c4 < CFE / 4; c4++) {
                const ulonglong2 w = ldp(&W1dp[c4 * CH + t]);
                const ulonglong2 f = ldp(&sCF[4 * c4]);
                ffma2(a, w.x, f.x);
                ffma2(a, w.y, f.y);
            }
            sC1[t] = hsum2(a);
        } else {
            const int vd = t - CH;
            #pragma unroll
            for (int c4 = 0; c4 < CFE / 4; c4++) {
                const ulonglong2 w = ldp(&Wvdp[c4 * DIMV + vd]);
                const ulonglong2 f = ldp(&sCF[4 * c4]);
                ffma2(a, w.x, f.x);
                ffma2(a, w.y, f.y);
            }
            sCV[vd] = hsum2(a);
        }
    }

    // ---- build F = [grouped | pos] -------------------------------------------
    for (int i = t; i < KNNK * CFE; i += 128) {
        const int k = i >> 6, c = i & 63;
        const float* np = xb + (size_t)sIdx[k] * CIN;
        sF[k * CR + c] = np[3 + c];
    }
    for (int i = t; i < KNNK * DIMV; i += 128) {
        const int k = i >> 4, vd = i & 15;
        const float* np = xb + (size_t)sIdx[k] * CIN;
        const float rx = np[0] - cx, ry = np[1] - cy, rz = np[2] - cz;
        sF[k * CR + CFE + vd] =
            Wh[vd * 3 + 0] * rx + Wh[vd * 3 + 1] * ry + Wh[vd * 3 + 2] * rz;
    }
    __syncthreads();

    const float bn_rs = rsqrtf(1.0f + EPSF);
    const int o  = t & 63;
    const int kg = t >> 6;     // 0: even k (warps 0-1), 1: odd k (warps 2-3)

    // ---- GEMM1: h1 = relu(bn1(W1g@Fk + c1)), 10 k per thread ------------------
    {
        ull acc[10];
        #pragma unroll
        for (int j = 0; j < 10; j++) acc[j] = 0ull;
        #pragma unroll 5
        for (int c4 = 0; c4 < CR / 4; c4++) {
            const ulonglong2 w = ldp(&W1gp[c4 * CH + o]);
            #pragma unroll
            for (int j = 0; j < 10; j++) {
                const ulonglong2 f = ldp(&sF[(kg + 2 * j) * CR + 4 * c4]);
                ffma2(acc[j], w.x, f.x);
                ffma2(acc[j], w.y, f.y);
            }
        }
        const float c1 = sC1[o];
        const float sc = g1[o] * bn_rs;
        const float bo = b1[o];
        #pragma unroll
        for (int j = 0; j < 10; j++)
            sH1[(kg + 2 * j) * CH + o] = fmaxf((hsum2(acc[j]) + c1) * sc + bo, 0.f);
    }
    // kg halves are independent through GEMM1->GEMM2: sync only within own half
    if (kg == 0) asm volatile("bar.sync 1, 64;" ::: "memory");
    else         asm volatile("bar.sync 2, 64;" ::: "memory");

    // ---- GEMM2 + fold relu/max over k into epilogue ----------------------------
    {
        ull acc[10];
        #pragma unroll
        for (int j = 0; j < 10; j++) acc[j] = 0ull;
        #pragma unroll 4
        for (int c4 = 0; c4 < CH / 4; c4++) {
            const ulonglong2 w = ldp(&W2p[c4 * CH + o]);
            #pragma unroll
            for (int j = 0; j < 10; j++) {
                const ulonglong2 f = ldp(&sH1[(kg + 2 * j) * CH + 4 * c4]);
                ffma2(acc[j], w.x, f.x);
                ffma2(acc[j], w.y, f.y);
            }
        }
        const float sc = g2[o] * bn_rs;
        const float bo = b2[o];
        float pm = 0.f;           // relu floor
        #pragma unroll
        for (int j = 0; j < 10; j++)
            pm = fmaxf(pm, hsum2(acc[j]) * sc + bo);
        sPM[kg * CH + o] = pm;
    }
    __syncthreads();

    if (t < CH)
        sFQ[t] = fmaxf(sPM[t], sPM[CH + t]);
    __syncthreads();

    // ---- q = relu(LN_256(W_q @ fq)); fused sum/sumsq reduction ------------------
    {
        float qv[2];
        #pragma unroll
        for (int r = 0; r < 2; r++) {
            const int oq = t + r * 128;
            ull a = 0ull;
            #pragma unroll
            for (int c4 = 0; c4 < CH / 4; c4++) {
                const ulonglong2 w = ldp(&Wqp[c4 * 256 + oq]);
                const ulonglong2 f = ldp(&sFQ[4 * c4]);
                ffma2(a, w.x, f.x);
                ffma2(a, w.y, f.y);
            }
            qv[r] = hsum2(a);
        }
        const float2 ssq  = block_sum2_128(qv[0] + qv[1],
                                           qv[0] * qv[0] + qv[1] * qv[1],
                                           sred, sbc);
        const float mean = ssq.x * (1.f / 256.f);
        const float var  = ssq.y * (1.f / 256.f) - mean * mean;
        const float inv  = rsqrtf(var + EPSF);
        #pragma unroll
        for (int r = 0; r < 2; r++) {
            const int oq = t + r * 128;
            sQ[oq] = fmaxf((qv[r] - mean) * inv * lnqw[oq] + lnqb[oq], 0.f);
        }
    }

    // ---- v-raw: vd = t&15, k0 = t>>4 (k = k0, k0+8, +16 if k0<4) ----------------
    {
        const int vd = t & 15;
        const int k0 = t >> 4;
        ull a0 = 0ull, a1 = 0ull, a2 = 0ull;
        const bool has2 = (k0 < 4);
        #pragma unroll 5
        for (int c4 = 0; c4 < CR / 4; c4++) {
            const ulonglong2 w  = ldp(&Wvgp[c4 * DIMV + vd]);
            const ulonglong2 f0 = ldp(&sF[k0 * CR + 4 * c4]);
            const ulonglong2 f1 = ldp(&sF[(k0 + 8) * CR + 4 * c4]);
            ffma2(a0, w.x, f0.x);  ffma2(a0, w.y, f0.y);
            ffma2(a1, w.x, f1.x);  ffma2(a1, w.y, f1.y);
            if (has2) {
                const ulonglong2 f2 = ldp(&sF[(k0 + 16) * CR + 4 * c4]);
                ffma2(a2, w.x, f2.x);  ffma2(a2, w.y, f2.y);
            }
        }
        const float cv = sCV[vd];
        sV[k0 * DIMV + vd]       = hsum2(a0) + cv;
        sV[(k0 + 8) * DIMV + vd] = hsum2(a1) + cv;
        if (has2) sV[(k0 + 16) * DIMV + vd] = hsum2(a2) + cv;
    }

    // ---- kk-raw: d = t&31, kb = t>>5, 5 k each ----------------------------------
    {
        const int d  = t & 31;
        const int kb = t >> 5;
        ull a[5];
        #pragma unroll
        for (int p = 0; p < 5; p++) a[p] = 0ull;
        #pragma unroll 5
        for (int c4 = 0; c4 < CR / 4; c4++) {
            const ulonglong2 w = ldp(&Wkgp[c4 * DIMK + d]);
            #pragma unroll
            for (int p = 0; p < 5; p++) {
                const ulonglong2 f = ldp(&sF[(kb + 4 * p) * CR + 4 * c4]);
                ffma2(a[p], w.x, f.x);
                ffma2(a[p], w.y, f.y);
            }
        }
        #pragma unroll
        for (int p = 0; p < 5; p++)
            sKK[(kb + 4 * p) * DIMK + d] = hsum2(a[p]);
    }
    __syncthreads();

    // ---- LN_16 over v (warp 0) || softmax over k (warp 2) -----------------------
    if (t < KNNK) {
        float s = 0.f, s2 = 0.f;
        #pragma unroll
        for (int vd = 0; vd < DIMV; vd++) {
            const float v = sV[t * DIMV + vd];
            s += v; s2 += v * v;
        }
        const float m   = s * (1.f / DIMV);
        const float var = s2 * (1.f / DIMV) - m * m;
        const float inv = rsqrtf(var + EPSF);
        #pragma unroll
        for (int vd = 0; vd < DIMV; vd++)
            sV[t * DIMV + vd] = (sV[t * DIMV + vd] - m) * inv * lnvw[vd] + lnvb[vd];
    } else if (t >= 64 && t < 64 + DIMK) {
        const int d = t - 64;
        float mx = -FLT_MAX;
        #pragma unroll
        for (int k = 0; k < KNNK; k++) mx = fmaxf(mx, sKK[k * DIMK + d]);
        float sum = 0.f;
        #pragma unroll
        for (int k = 0; k < KNNK; k++) {
            const float e = expf(sKK[k * DIMK + d] - mx);
            sKK[k * DIMK + d] = e;
            sum += e;
        }
        const float inv = 1.f / sum;
        #pragma unroll
        for (int k = 0; k < KNNK; k++) sKK[k * DIMK + d] *= inv;
    }
    __syncthreads();

    // ---- kv[d][v] = sum_k kk[k][d] * v[k][v] -------------------------------------
    for (int i = t; i < DIMK * DIMV; i += 128) {
        const int d = i >> 4, vd = i & 15;
        float acc = 0.f;
        #pragma unroll
        for (int k = 0; k < KNNK; k++)
            acc += sKK[k * DIMK + d] * sV[k * DIMV + vd];
        sKV[i] = acc;
    }
    __syncthreads();

    // ---- out = LN_128(q @ kv), fused stats, write transposed -----------------------
    {
        const int h = t >> 4, vd = t & 15;
        float acc = 0.f;
        #pragma unroll
        for (int d = 0; d < DIMK; d++)
            acc += sQ[h * DIMK + d] * sKV[d * DIMV + vd];

        const float2 ssq  = block_sum2_128(acc, acc * acc, sred, sbc);
        const float mean = ssq.x * (1.f / COUT);
        const float var  = ssq.y * (1.f / COUT) - mean * mean;
        const float inv  = rsqrtf(var + EPSF);
        const float ov   = (acc - mean) * inv * lnow[t] + lnob[t];

        out[XYZ_TOT + ((size_t)b * COUT + t) * NN + n] = ov;
    }
}

// ---------------------------------------------------------------------------
// launch
// ---------------------------------------------------------------------------
extern "C" void kernel_launch(void* const* d_in, const int* in_sizes, int n_in,
                              void* d_out, int out_size)
{
    const float* x    = (const float*)d_in[0];
    const float* Wh   = (const float*)d_in[1];
    const float* W1   = (const float*)d_in[2];
    const float* g1   = (const float*)d_in[3];
    const float* b1   = (const float*)d_in[4];
    const float* W2   = (const float*)d_in[5];
    const float* g2   = (const float*)d_in[6];
    const float* b2   = (const float*)d_in[7];
    const float* Wq   = (const float*)d_in[8];
    const float* lnqw = (const float*)d_in[9];
    const float* lnqb = (const float*)d_in[10];
    const float* Wv   = (const float*)d_in[11];
    const float* lnvw = (const float*)d_in[12];
    const float* lnvb = (const float*)d_in[13];
    const float* Wk   = (const float*)d_in[14];
    const float* lnow = (const float*)d_in[15];
    const float* lnob = (const float*)d_in[16];
    float* out = (float*)d_out;

    const int pack_total = (CR/4)*CH + (CFE/4)*CH + (CH/4)*CH + (CH/4)*NHEAD*DIMK
                         + (CR/4)*DIMV + (CFE/4)*DIMV + (CR/4)*DIMK;
    pack_weights<<<(pack_total + 127) / 128, 128>>>(W1, W2, Wq, Wv, Wk);

    const int knn_smem = (4 * NN + 8 * NN) * (int)sizeof(float);  // 96 KB
    cudaFuncSetAttribute(knn_kernel,
                         cudaFuncAttributeMaxDynamicSharedMemorySize, knn_smem);
    knn_kernel<<<BB * (NN / 8), 256, knn_smem>>>(x);

    fused_kernel<<<BB * NN, 128>>>(x, Wh,
                                   g1, b1, g2, b2,
                                   lnqw, lnqb, lnvw, lnvb,
                                   lnow, lnob,
                                   out);
}

// round 12
// speedup vs baseline: 1.3896x; 1.0825x over previous
#include <cuda_runtime.h>
#include <float.h>
#include <math.h>

// ---------------------------------------------------------------------------
// Problem constants
// ---------------------------------------------------------------------------
#define BB    8
#define NN    2048
#define KNNK  20
#define CIN   67          // 3 xyz + 64 feat
#define CFE   64
#define CCC   144         // 64 gpn + 64 center + 16 pos
#define CR    80          // reduced per-k channels: 64 grouped + 16 pos
#define CH    64
#define DIMV  16
#define DIMK  32
#define NHEAD 8
#define COUT  128
#define EPSF  1e-5f
#define XYZ_TOT (BB*NN*3)

typedef unsigned long long ull;

// scratch (no allocation allowed -> __device__ globals)
__device__ int    g_idx[BB * NN * KNNK];
__device__ float4 W1gp[(CR/4) * CH];            // [c4 0..19][o]
__device__ float4 W1dp[(CFE/4) * CH];           // [c4 0..15][o]  W1[:,64:128]-W1[:,:64]
__device__ float4 W2p [(CH/4)  * CH];           // [c4][o]
__device__ float4 Wqp [(CH/4)  * (NHEAD*DIMK)]; // [c4][o]
__device__ float4 Wvgp[(CR/4) * DIMV];          // [c4 0..19][vd]
__device__ float4 Wvdp[(CFE/4) * DIMV];         // [c4 0..15][vd]
__device__ float4 Wkgp[(CR/4) * DIMK];          // [c4 0..19][d]

// ---------------------------------------------------------------------------
// packed dual-fp32 FMA helpers
// ---------------------------------------------------------------------------
__device__ __forceinline__ void ffma2(ull& d, ull a, ull b)
{
    asm("fma.rn.f32x2 %0, %1, %2, %0;" : "+l"(d) : "l"(a), "l"(b));
}
__device__ __forceinline__ float hsum2(ull v)
{
    float lo, hi;
    asm("mov.b64 {%0, %1}, %2;" : "=f"(lo), "=f"(hi) : "l"(v));
    return lo + hi;
}
__device__ __forceinline__ ulonglong2 ldp(const void* p)
{
    return *(const ulonglong2*)p;
}

// ---------------------------------------------------------------------------
// Kernel 0: pack weights (transposed + center-folded layouts)
// ---------------------------------------------------------------------------
__global__ void pack_weights(const float* __restrict__ W1, const float* __restrict__ W2,
                             const float* __restrict__ Wq, const float* __restrict__ Wv,
                             const float* __restrict__ Wk)
{
    int i = blockIdx.x * blockDim.x + threadIdx.x;

    if (i < (CR/4)*CH) {
        int c4 = i >> 6, o = i & 63;
        int col = (c4 < 16) ? 4 * c4 : 128 + 4 * (c4 - 16);
        W1gp[i] = *(const float4*)&W1[o * CCC + col];
        return;
    }
    i -= (CR/4)*CH;
    if (i < (CFE/4)*CH) {
        int c4 = i >> 6, o = i & 63;
        float4 a = *(const float4*)&W1[o * CCC + 64 + 4 * c4];
        float4 b = *(const float4*)&W1[o * CCC + 4 * c4];
        W1dp[i] = make_float4(a.x - b.x, a.y - b.y, a.z - b.z, a.w - b.w);
        return;
    }
    i -= (CFE/4)*CH;
    if (i < (CH/4)*CH) {
        int c4 = i >> 6, o = i & 63;
        W2p[i] = *(const float4*)&W2[o * CH + 4 * c4];
        return;
    }
    i -= (CH/4)*CH;
    if (i < (CH/4)*NHEAD*DIMK) {
        int c4 = i >> 8, o = i & 255;
        Wqp[i] = *(const float4*)&Wq[o * CH + 4 * c4];
        return;
    }
    i -= (CH/4)*NHEAD*DIMK;
    if (i < (CR/4)*DIMV) {
        int c4 = i >> 4, vd = i & 15;
        int col = (c4 < 16) ? 4 * c4 : 128 + 4 * (c4 - 16);
        Wvgp[i] = *(const float4*)&Wv[vd * CCC + col];
        return;
    }
    i -= (CR/4)*DIMV;
    if (i < (CFE/4)*DIMV) {
        int c4 = i >> 4, vd = i & 15;
        float4 a = *(const float4*)&Wv[vd * CCC + 64 + 4 * c4];
        float4 b = *(const float4*)&Wv[vd * CCC + 4 * c4];
        Wvdp[i] = make_float4(a.x - b.x, a.y - b.y, a.z - b.z, a.w - b.w);
        return;
    }
    i -= (CFE/4)*DIMV;
    if (i < (CR/4)*DIMK) {
        int c4 = i >> 5, d = i & 31;
        int col = (c4 < 16) ? 4 * c4 : 128 + 4 * (c4 - 16);
        Wkgp[i] = *(const float4*)&Wk[d * CCC + col];
    }
}

// ---------------------------------------------------------------------------
// Kernel 1: brute-force KNN; per-lane top-2 cache, rare rescans
// ---------------------------------------------------------------------------
__global__ void knn_kernel(const float* __restrict__ x)
{
    extern __shared__ float sm[];
    float* sx   = sm;
    float* sy   = sx + NN;
    float* sz   = sy + NN;
    float* ss   = sz + NN;
    float* dist = ss + NN;      // [8][NN]

    const int b     = blockIdx.x >> 8;
    const int qbase = (blockIdx.x & 255) << 3;
    const int t     = threadIdx.x;
    const int w     = t >> 5;
    const int lane  = t & 31;

    for (int j = t; j < NN; j += 256) {
        const float* p = x + ((size_t)b * NN + j) * CIN;
        float a0 = p[0], a1 = p[1], a2 = p[2];
        sx[j] = a0; sy[j] = a1; sz[j] = a2;
        ss[j] = a0 * a0 + a1 * a1 + a2 * a2;
    }
    __syncthreads();

    const int n = qbase + w;
    const float qx = sx[n], qy = sy[n], qz = sz[n], sq = ss[n];
    float* dw = dist + w * NN;

    float v1 = FLT_MAX, v2 = FLT_MAX;
    int   i1 = 0x7fffffff, i2 = 0x7fffffff;
    for (int j = lane; j < NN; j += 32) {
        const float dot = qx * sx[j] + qy * sy[j] + qz * sz[j];
        const float d   = -2.0f * dot + sq + ss[j];
        dw[j] = d;
        if (d < v1)      { v2 = v1; i2 = i1; v1 = d; i1 = j; }
        else if (d < v2) { v2 = d;  i2 = j; }
    }
    __syncwarp();

    for (int sel = 0; sel < KNNK; sel++) {
        float wv = v1;
        int   wi = i1;
        #pragma unroll
        for (int o = 16; o; o >>= 1) {
            float ov = __shfl_xor_sync(0xffffffffu, wv, o);
            int   oi = __shfl_xor_sync(0xffffffffu, wi, o);
            if (ov < wv || (ov == wv && oi < wi)) { wv = ov; wi = oi; }
        }
        if (lane == 0)
            g_idx[((size_t)b * NN + n) * KNNK + sel] = wi;
        if (i1 == wi) {
            dw[wi] = FLT_MAX;
            v1 = v2; i1 = i2;
            v2 = FLT_MAX; i2 = 0x7fffffff;
            if (v1 == FLT_MAX) {
                for (int j = lane; j < NN; j += 32) {
                    const float d = dw[j];
                    if (d < v1)      { v2 = v1; i2 = i1; v1 = d; i1 = j; }
                    else if (d < v2) { v2 = d;  i2 = j; }
                }
            }
        }
        __syncwarp();
    }
}

// ---------------------------------------------------------------------------
// fused block reduction: component-wise sum of float4 over 128 threads
// ---------------------------------------------------------------------------
__device__ __forceinline__ float4 block_sum4_128(float4 v, float4* sred, float4* sbc)
{
    #pragma unroll
    for (int o = 16; o; o >>= 1) {
        v.x += __shfl_xor_sync(0xffffffffu, v.x, o);
        v.y += __shfl_xor_sync(0xffffffffu, v.y, o);
        v.z += __shfl_xor_sync(0xffffffffu, v.z, o);
        v.w += __shfl_xor_sync(0xffffffffu, v.w, o);
    }
    if ((threadIdx.x & 31) == 0) sred[threadIdx.x >> 5] = v;
    __syncthreads();
    if (threadIdx.x == 0) {
        float4 a = sred[0], b = sred[1], c = sred[2], d = sred[3];
        *sbc = make_float4(a.x + b.x + c.x + d.x, a.y + b.y + c.y + d.y,
                           a.z + b.z + c.z + d.z, a.w + b.w + c.w + d.w);
    }
    __syncthreads();
    return *sbc;
}

// ---------------------------------------------------------------------------
// Kernel 2: fused block, TWO points per block (shared weight loads).
// ---------------------------------------------------------------------------
__global__ void __launch_bounds__(128)
fused_kernel(const float* __restrict__ x,
             const float* __restrict__ Wh,
             const float* __restrict__ g1, const float* __restrict__ b1,
             const float* __restrict__ g2, const float* __restrict__ b2,
             const float* __restrict__ lnqw, const float* __restrict__ lnqb,
             const float* __restrict__ lnvw, const float* __restrict__ lnvb,
             const float* __restrict__ lnow, const float* __restrict__ lnob,
             float* __restrict__ out)
{
    const int bn0 = blockIdx.x << 1;       // two consecutive points, same batch
    const int b   = bn0 >> 11;
    const int n0  = bn0 & (NN - 1);
    const int t   = threadIdx.x;

    __shared__ __align__(16) float sF [2][KNNK * CR];
    __shared__ __align__(16) float sH1[2][KNNK * CH];
    __shared__ __align__(16) float sPM[2][2 * CH];
    __shared__ __align__(16) float sFQ[2][CH];
    __shared__ __align__(16) float sQ [2][NHEAD * DIMK];
    __shared__ __align__(16) float sV [2][KNNK * DIMV];
    __shared__ __align__(16) float sKK[2][KNNK * DIMK];
    __shared__ __align__(16) float sKV[2][DIMK * DIMV];
    __shared__ __align__(16) float sCF[2][CFE];
    __shared__ __align__(16) float sC1[2][CH];
    __shared__ __align__(16) float sCV[2][DIMV];
    __shared__ int    sIdx[2][KNNK];
    __shared__ float4 sred[4];
    __shared__ float4 sbc[1];

    const float* xb  = x + (size_t)b * NN * CIN;
    const float* xc0 = xb + (size_t)n0 * CIN;
    const float* xc1 = xc0 + CIN;

    // xyz passthrough (off critical path)
    if (t < 6) {
        const int p = t / 3, c = t - 3 * p;
        out[(size_t)(bn0 + p) * 3 + c] = (p ? xc1 : xc0)[c];
    }
    {   // center features: t -> (p = t>>6, c = t&63)
        const int p = t >> 6, c = t & 63;
        sCF[p][c] = (p ? xc1 : xc0)[3 + c];
    }
    if (t < 2 * KNNK) {
        const int p = t / KNNK, kk = t - p * KNNK;
        sIdx[p][kk] = g_idx[(size_t)(bn0 + p) * KNNK + kk];
    }
    __syncthreads();

    // ---- per-point constants (center-folded): C1 (all threads), CV (t<32) ----
    {
        const int p = t >> 6, oo = t & 63;
        ull a = 0ull;
        #pragma unroll
        for (int c4 = 0; c4 < CFE / 4; c4++) {
            const ulonglong2 w = ldp(&W1dp[c4 * CH + oo]);
            const ulonglong2 f = ldp(&sCF[p][4 * c4]);
            ffma2(a, w.x, f.x);
            ffma2(a, w.y, f.y);
        }
        sC1[p][oo] = hsum2(a);
    }
    if (t < 32) {
        const int p = t >> 4, vd = t & 15;
        ull a = 0ull;
        #pragma unroll
        for (int c4 = 0; c4 < CFE / 4; c4++) {
            const ulonglong2 w = ldp(&Wvdp[c4 * DIMV + vd]);
            const ulonglong2 f = ldp(&sCF[p][4 * c4]);
            ffma2(a, w.x, f.x);
            ffma2(a, w.y, f.y);
        }
        sCV[p][vd] = hsum2(a);
    }

    // ---- build F = [grouped | pos] for both points ----------------------------
    for (int i = t; i < 2 * KNNK * CFE; i += 128) {
        const int p = i / (KNNK * CFE);
        const int r = i - p * (KNNK * CFE);
        const int k = r >> 6, c = r & 63;
        const float* np = xb + (size_t)sIdx[p][k] * CIN;
        sF[p][k * CR + c] = np[3 + c];
    }
    {
        const float c0x = xc0[0], c0y = xc0[1], c0z = xc0[2];
        const float c1x = xc1[0], c1y = xc1[1], c1z = xc1[2];
        for (int i = t; i < 2 * KNNK * DIMV; i += 128) {
            const int p = i / (KNNK * DIMV);
            const int r = i - p * (KNNK * DIMV);
            const int k = r >> 4, vd = r & 15;
            const float* np = xb + (size_t)sIdx[p][k] * CIN;
            const float rx = np[0] - (p ? c1x : c0x);
            const float ry = np[1] - (p ? c1y : c0y);
            const float rz = np[2] - (p ? c1z : c0z);
            sF[p][k * CR + CFE + vd] =
                Wh[vd * 3 + 0] * rx + Wh[vd * 3 + 1] * ry + Wh[vd * 3 + 2] * rz;
        }
    }
    __syncthreads();

    const float bn_rs = rsqrtf(1.0f + EPSF);
    const int o  = t & 63;
    const int kg = t >> 6;     // k-parity

    // ---- GEMM1 both points, shared weight loads -------------------------------
    {
        ull a0[10], a1[10];
        #pragma unroll
        for (int j = 0; j < 10; j++) { a0[j] = 0ull; a1[j] = 0ull; }
        #pragma unroll 2
        for (int c4 = 0; c4 < CR / 4; c4++) {
            const ulonglong2 w = ldp(&W1gp[c4 * CH + o]);
            #pragma unroll
            for (int j = 0; j < 10; j++) {
                const ulonglong2 f0 = ldp(&sF[0][(kg + 2 * j) * CR + 4 * c4]);
                ffma2(a0[j], w.x, f0.x);  ffma2(a0[j], w.y, f0.y);
                const ulonglong2 f1 = ldp(&sF[1][(kg + 2 * j) * CR + 4 * c4]);
                ffma2(a1[j], w.x, f1.x);  ffma2(a1[j], w.y, f1.y);
            }
        }
        const float c10 = sC1[0][o], c11 = sC1[1][o];
        const float sc  = g1[o] * bn_rs;
        const float bo  = b1[o];
        #pragma unroll
        for (int j = 0; j < 10; j++) {
            sH1[0][(kg + 2 * j) * CH + o] = fmaxf((hsum2(a0[j]) + c10) * sc + bo, 0.f);
            sH1[1][(kg + 2 * j) * CH + o] = fmaxf((hsum2(a1[j]) + c11) * sc + bo, 0.f);
        }
    }
    // kg halves independent through GEMM1->GEMM2 (both points)
    if (kg == 0) asm volatile("bar.sync 1, 64;" ::: "memory");
    else         asm volatile("bar.sync 2, 64;" ::: "memory");

    // ---- GEMM2 both points + fold relu/max over k ------------------------------
    {
        ull a0[10], a1[10];
        #pragma unroll
        for (int j = 0; j < 10; j++) { a0[j] = 0ull; a1[j] = 0ull; }
        #pragma unroll 2
        for (int c4 = 0; c4 < CH / 4; c4++) {
            const ulonglong2 w = ldp(&W2p[c4 * CH + o]);
            #pragma unroll
            for (int j = 0; j < 10; j++) {
                const ulonglong2 f0 = ldp(&sH1[0][(kg + 2 * j) * CH + 4 * c4]);
                ffma2(a0[j], w.x, f0.x);  ffma2(a0[j], w.y, f0.y);
                const ulonglong2 f1 = ldp(&sH1[1][(kg + 2 * j) * CH + 4 * c4]);
                ffma2(a1[j], w.x, f1.x);  ffma2(a1[j], w.y, f1.y);
            }
        }
        const float sc = g2[o] * bn_rs;
        const float bo = b2[o];
        float pm0 = 0.f, pm1 = 0.f;   // relu floor
        #pragma unroll
        for (int j = 0; j < 10; j++) {
            pm0 = fmaxf(pm0, hsum2(a0[j]) * sc + bo);
            pm1 = fmaxf(pm1, hsum2(a1[j]) * sc + bo);
        }
        sPM[0][kg * CH + o] = pm0;
        sPM[1][kg * CH + o] = pm1;
    }
    __syncthreads();

    {   // feature_q = max over kg halves; t -> (p, oo)
        const int p = t >> 6, oo = t & 63;
        sFQ[p][oo] = fmaxf(sPM[p][oo], sPM[p][CH + oo]);
    }
    __syncthreads();

    // ---- q = relu(LN_256(Wq @ fq)) for both points, shared weights --------------
    {
        float qv0[2], qv1[2];
        #pragma unroll
        for (int r = 0; r < 2; r++) {
            const int oq = t + r * 128;
            ull aA = 0ull, aB = 0ull;
            #pragma unroll
            for (int c4 = 0; c4 < CH / 4; c4++) {
                const ulonglong2 w  = ldp(&Wqp[c4 * 256 + oq]);
                const ulonglong2 fA = ldp(&sFQ[0][4 * c4]);
                const ulonglong2 fB = ldp(&sFQ[1][4 * c4]);
                ffma2(aA, w.x, fA.x);  ffma2(aA, w.y, fA.y);
                ffma2(aB, w.x, fB.x);  ffma2(aB, w.y, fB.y);
            }
            qv0[r] = hsum2(aA);
            qv1[r] = hsum2(aB);
        }
        const float4 ssq = block_sum4_128(
            make_float4(qv0[0] + qv0[1], qv0[0] * qv0[0] + qv0[1] * qv0[1],
                        qv1[0] + qv1[1], qv1[0] * qv1[0] + qv1[1] * qv1[1]),
            sred, sbc);
        const float m0 = ssq.x * (1.f / 256.f);
        const float i0 = rsqrtf(ssq.y * (1.f / 256.f) - m0 * m0 + EPSF);
        const float m1 = ssq.z * (1.f / 256.f);
        const float i1 = rsqrtf(ssq.w * (1.f / 256.f) - m1 * m1 + EPSF);
        #pragma unroll
        for (int r = 0; r < 2; r++) {
            const int oq = t + r * 128;
            const float lw = lnqw[oq], lb = lnqb[oq];
            sQ[0][oq] = fmaxf((qv0[r] - m0) * i0 * lw + lb, 0.f);
            sQ[1][oq] = fmaxf((qv1[r] - m1) * i1 * lw + lb, 0.f);
        }
    }

    // ---- v-raw both points: vd = t&15, k0 = t>>4 (k = k0, k0+8, +16 if k0<4) ----
    {
        const int vd = t & 15;
        const int k0 = t >> 4;
        ull p0a = 0ull, p0b = 0ull, p0c = 0ull;
        ull p1a = 0ull, p1b = 0ull, p1c = 0ull;
        const bool has2 = (k0 < 4);
        #pragma unroll 2
        for (int c4 = 0; c4 < CR / 4; c4++) {
            const ulonglong2 w  = ldp(&Wvgp[c4 * DIMV + vd]);
            {
                const ulonglong2 f0 = ldp(&sF[0][k0 * CR + 4 * c4]);
                const ulonglong2 f1 = ldp(&sF[0][(k0 + 8) * CR + 4 * c4]);
                ffma2(p0a, w.x, f0.x);  ffma2(p0a, w.y, f0.y);
                ffma2(p0b, w.x, f1.x);  ffma2(p0b, w.y, f1.y);
                if (has2) {
                    const ulonglong2 f2 = ldp(&sF[0][(k0 + 16) * CR + 4 * c4]);
                    ffma2(p0c, w.x, f2.x);  ffma2(p0c, w.y, f2.y);
                }
            }
            {
                const ulonglong2 f0 = ldp(&sF[1][k0 * CR + 4 * c4]);
                const ulonglong2 f1 = ldp(&sF[1][(k0 + 8) * CR + 4 * c4]);
                ffma2(p1a, w.x, f0.x);  ffma2(p1a, w.y, f0.y);
                ffma2(p1b, w.x, f1.x);  ffma2(p1b, w.y, f1.y);
                if (has2) {
                    const ulonglong2 f2 = ldp(&sF[1][(k0 + 16) * CR + 4 * c4]);
                    ffma2(p1c, w.x, f2.x);  ffma2(p1c, w.y, f2.y);
                }
            }
        }
        const float cv0 = sCV[0][vd], cv1 = sCV[1][vd];
        sV[0][k0 * DIMV + vd]       = hsum2(p0a) + cv0;
        sV[0][(k0 + 8) * DIMV + vd] = hsum2(p0b) + cv0;
        sV[1][k0 * DIMV + vd]       = hsum2(p1a) + cv1;
        sV[1][(k0 + 8) * DIMV + vd] = hsum2(p1b) + cv1;
        if (has2) {
            sV[0][(k0 + 16) * DIMV + vd] = hsum2(p0c) + cv0;
            sV[1][(k0 + 16) * DIMV + vd] = hsum2(p1c) + cv1;
        }
    }

    // ---- kk-raw both points: d = t&31, kb = t>>5, 5 k each ----------------------
    {
        const int d  = t & 31;
        const int kb = t >> 5;
        ull a0[5], a1[5];
        #pragma unroll
        for (int p = 0; p < 5; p++) { a0[p] = 0ull; a1[p] = 0ull; }
        #pragma unroll 2
        for (int c4 = 0; c4 < CR / 4; c4++) {
            const ulonglong2 w = ldp(&Wkgp[c4 * DIMK + d]);
            #pragma unroll
            for (int p = 0; p < 5; p++) {
                const ulonglong2 f0 = ldp(&sF[0][(kb + 4 * p) * CR + 4 * c4]);
                ffma2(a0[p], w.x, f0.x);  ffma2(a0[p], w.y, f0.y);
                const ulonglong2 f1 = ldp(&sF[1][(kb + 4 * p) * CR + 4 * c4]);
                ffma2(a1[p], w.x, f1.x);  ffma2(a1[p], w.y, f1.y);
            }
        }
        #pragma unroll
        for (int p = 0; p < 5; p++) {
            sKK[0][(kb + 4 * p) * DIMK + d] = hsum2(a0[p]);
            sKK[1][(kb + 4 * p) * DIMK + d] = hsum2(a1[p]);
        }
    }
    __syncthreads();

    // ---- LN_16 over v (threads 0-39) || softmax over k (threads 64-127) ---------
    if (t < 2 * KNNK) {
        const int p = t / KNNK, row = t - p * KNNK;
        float s = 0.f, s2 = 0.f;
        #pragma unroll
        for (int vd = 0; vd < DIMV; vd++) {
            const float v = sV[p][row * DIMV + vd];
            s += v; s2 += v * v;
        }
        const float m   = s * (1.f / DIMV);
        const float var = s2 * (1.f / DIMV) - m * m;
        const float inv = rsqrtf(var + EPSF);
        #pragma unroll
        for (int vd = 0; vd < DIMV; vd++)
            sV[p][row * DIMV + vd] =
                (sV[p][row * DIMV + vd] - m) * inv * lnvw[vd] + lnvb[vd];
    } else if (t >= 64) {
        const int idx = t - 64;         // 64 threads = 2 points x 32 dims
        const int p = idx >> 5, d = idx & 31;
        float mx = -FLT_MAX;
        #pragma unroll
        for (int k = 0; k < KNNK; k++) mx = fmaxf(mx, sKK[p][k * DIMK + d]);
        float sum = 0.f;
        #pragma unroll
        for (int k = 0; k < KNNK; k++) {
            const float e = expf(sKK[p][k * DIMK + d] - mx);
            sKK[p][k * DIMK + d] = e;
            sum += e;
        }
        const float inv = 1.f / sum;
        #pragma unroll
        for (int k = 0; k < KNNK; k++) sKK[p][k * DIMK + d] *= inv;
    }
    __syncthreads();

    // ---- kv[p][d][v] = sum_k kk[k][d] * v[k][v] ----------------------------------
    for (int i = t; i < 2 * DIMK * DIMV; i += 128) {
        const int p = i >> 9;
        const int r = i & 511;
        const int d = r >> 4, vd = r & 15;
        float acc = 0.f;
        #pragma unroll
        for (int k = 0; k < KNNK; k++)
            acc += sKK[p][k * DIMK + d] * sV[p][k * DIMV + vd];
        sKV[p][r] = acc;
    }
    __syncthreads();

    // ---- out = LN_128(q @ kv) for both points, write transposed --------------------
    {
        const int h = t >> 4, vd = t & 15;
        float acc0 = 0.f, acc1 = 0.f;
        #pragma unroll
        for (int d = 0; d < DIMK; d++) {
            acc0 += sQ[0][h * DIMK + d] * sKV[0][d * DIMV + vd];
            acc1 += sQ[1][h * DIMK + d] * sKV[1][d * DIMV + vd];
        }
        const float4 ssq = block_sum4_128(
            make_float4(acc0, acc0 * acc0, acc1, acc1 * acc1), sred, sbc);
        const float m0 = ssq.x * (1.f / COUT);
        const float i0 = rsqrtf(ssq.y * (1.f / COUT) - m0 * m0 + EPSF);
        const float m1 = ssq.z * (1.f / COUT);
        const float i1 = rsqrtf(ssq.w * (1.f / COUT) - m1 * m1 + EPSF);
        const float lw = lnow[t], lb = lnob[t];
        float* op = out + XYZ_TOT + ((size_t)b * COUT + t) * NN + n0;
        op[0] = (acc0 - m0) * i0 * lw + lb;
        op[1] = (acc1 - m1) * i1 * lw + lb;
    }
}

// ---------------------------------------------------------------------------
// launch
// ---------------------------------------------------------------------------
extern "C" void kernel_launch(void* const* d_in, const int* in_sizes, int n_in,
                              void* d_out, int out_size)
{
    const float* x    = (const float*)d_in[0];
    const float* Wh   = (const float*)d_in[1];
    const float* W1   = (const float*)d_in[2];
    const float* g1   = (const float*)d_in[3];
    const float* b1   = (const float*)d_in[4];
    const float* W2   = (const float*)d_in[5];
    const float* g2   = (const float*)d_in[6];
    const float* b2   = (const float*)d_in[7];
    const float* Wq   = (const float*)d_in[8];
    const float* lnqw = (const float*)d_in[9];
    const float* lnqb = (const float*)d_in[10];
    const float* Wv   = (const float*)d_in[11];
    const float* lnvw = (const float*)d_in[12];
    const float* lnvb = (const float*)d_in[13];
    const float* Wk   = (const float*)d_in[14];
    const float* lnow = (const float*)d_in[15];
    const float* lnob = (const float*)d_in[16];
    float* out = (float*)d_out;

    const int pack_total = (CR/4)*CH + (CFE/4)*CH + (CH/4)*CH + (CH/4)*NHEAD*DIMK
                         + (CR/4)*DIMV + (CFE/4)*DIMV + (CR/4)*DIMK;
    pack_weights<<<(pack_total + 127) / 128, 128>>>(W1, W2, Wq, Wv, Wk);

    const int knn_smem = (4 * NN + 8 * NN) * (int)sizeof(float);  // 96 KB
    cudaFuncSetAttribute(knn_kernel,
                         cudaFuncAttributeMaxDynamicSharedMemorySize, knn_smem);
    knn_kernel<<<BB * (NN / 8), 256, knn_smem>>>(x);

    fused_kernel<<<BB * NN / 2, 128>>>(x, Wh,
                                       g1, b1, g2, b2,
                                       lnqw, lnqb, lnvw, lnvb,
                                       lnow, lnob,
                                       out);
}

// round 14
// speedup vs baseline: 1.8125x; 1.3044x over previous
#include <cuda_runtime.h>
#include <float.h>
#include <math.h>

// ---------------------------------------------------------------------------
// Problem constants
// ---------------------------------------------------------------------------
#define BB    8
#define NN    2048
#define KNNK  20
#define CIN   67          // 3 xyz + 64 feat
#define CFE   64
#define CCC   144         // 64 gpn + 64 center + 16 pos
#define CR    80
#define CH    64
#define DIMV  16
#define DIMK  32
#define NHEAD 8
#define COUT  128
#define EPSF  1e-5f
#define XYZ_TOT (BB*NN*3)
#define GPW   112         // per-point transform width: 64 (G1) + 16 (GV) + 32 (GK)
#define GP_G1 0
#define GP_GV 64
#define GP_GK 80

typedef unsigned long long ull;

// scratch (no allocation allowed -> __device__ globals)
__device__ int    g_idx[BB * NN * KNNK];
__device__ float4 W1gp[(CR/4) * CH];            // [c4 0..19][o]  (c4<16: feat, >=16: pos)
__device__ float4 W1dp[(CFE/4) * CH];           // center-fold diff for W1
__device__ float4 W2p [(CH/4)  * CH];
__device__ float4 Wqp [(CH/4)  * (NHEAD*DIMK)];
__device__ float4 Wvgp[(CR/4) * DIMV];
__device__ float4 Wvdp[(CFE/4) * DIMV];
__device__ float4 Wkgp[(CR/4) * DIMK];
__device__ float  g_GP[BB * NN * GPW];          // per-point feat transforms (7.3 MB)

// ---------------------------------------------------------------------------
// packed dual-fp32 FMA helpers
// ---------------------------------------------------------------------------
__device__ __forceinline__ void ffma2(ull& d, ull a, ull b)
{
    asm("fma.rn.f32x2 %0, %1, %2, %0;" : "+l"(d) : "l"(a), "l"(b));
}
__device__ __forceinline__ float hsum2(ull v)
{
    float lo, hi;
    asm("mov.b64 {%0, %1}, %2;" : "=f"(lo), "=f"(hi) : "l"(v));
    return lo + hi;
}
__device__ __forceinline__ ulonglong2 ldp(const void* p)
{
    return *(const ulonglong2*)p;
}

// ---------------------------------------------------------------------------
// Kernel 0: pack weights (transposed + center-folded layouts)
// ---------------------------------------------------------------------------
__global__ void pack_weights(const float* __restrict__ W1, const float* __restrict__ W2,
                             const float* __restrict__ Wq, const float* __restrict__ Wv,
                             const float* __restrict__ Wk)
{
    int i = blockIdx.x * blockDim.x + threadIdx.x;

    if (i < (CR/4)*CH) {
        int c4 = i >> 6, o = i & 63;
        int col = (c4 < 16) ? 4 * c4 : 128 + 4 * (c4 - 16);
        W1gp[i] = *(const float4*)&W1[o * CCC + col];
        return;
    }
    i -= (CR/4)*CH;
    if (i < (CFE/4)*CH) {
        int c4 = i >> 6, o = i & 63;
        float4 a = *(const float4*)&W1[o * CCC + 64 + 4 * c4];
        float4 b = *(const float4*)&W1[o * CCC + 4 * c4];
        W1dp[i] = make_float4(a.x - b.x, a.y - b.y, a.z - b.z, a.w - b.w);
        return;
    }
    i -= (CFE/4)*CH;
    if (i < (CH/4)*CH) {
        int c4 = i >> 6, o = i & 63;
        W2p[i] = *(const float4*)&W2[o * CH + 4 * c4];
        return;
    }
    i -= (CH/4)*CH;
    if (i < (CH/4)*NHEAD*DIMK) {
        int c4 = i >> 8, o = i & 255;
        Wqp[i] = *(const float4*)&Wq[o * CH + 4 * c4];
        return;
    }
    i -= (CH/4)*NHEAD*DIMK;
    if (i < (CR/4)*DIMV) {
        int c4 = i >> 4, vd = i & 15;
        int col = (c4 < 16) ? 4 * c4 : 128 + 4 * (c4 - 16);
        Wvgp[i] = *(const float4*)&Wv[vd * CCC + col];
        return;
    }
    i -= (CR/4)*DIMV;
    if (i < (CFE/4)*DIMV) {
        int c4 = i >> 4, vd = i & 15;
        float4 a = *(const float4*)&Wv[vd * CCC + 64 + 4 * c4];
        float4 b = *(const float4*)&Wv[vd * CCC + 4 * c4];
        Wvdp[i] = make_float4(a.x - b.x, a.y - b.y, a.z - b.z, a.w - b.w);
        return;
    }
    i -= (CFE/4)*DIMV;
    if (i < (CR/4)*DIMK) {
        int c4 = i >> 5, d = i & 31;
        int col = (c4 < 16) ? 4 * c4 : 128 + 4 * (c4 - 16);
        Wkgp[i] = *(const float4*)&Wk[d * CCC + col];
    }
}

// ---------------------------------------------------------------------------
// Kernel 0b: per-point feat transforms GP = [W1f@feat | Wvf@feat | Wkf@feat]
// layout per point: [0..63]=G1, [64..79]=GV, [80..111]=GK
// ---------------------------------------------------------------------------
__global__ void __launch_bounds__(128)
precompute_points(const float* __restrict__ x)
{
    const int pt = blockIdx.x;
    const int t  = threadIdx.x;
    __shared__ __align__(16) float sf[CFE];

    const float* xc = x + (size_t)pt * CIN;
    if (t < CFE) sf[t] = xc[3 + t];
    __syncthreads();

    if (t >= GPW) return;
    ull a = 0ull;
    if (t < GP_GV) {
        #pragma unroll
        for (int c4 = 0; c4 < 16; c4++) {
            const ulonglong2 w = ldp(&W1gp[c4 * CH + t]);
            const ulonglong2 f = ldp(&sf[4 * c4]);
            ffma2(a, w.x, f.x);
            ffma2(a, w.y, f.y);
        }
    } else if (t < GP_GK) {
        const int vd = t - GP_GV;
        #pragma unroll
        for (int c4 = 0; c4 < 16; c4++) {
            const ulonglong2 w = ldp(&Wvgp[c4 * DIMV + vd]);
            const ulonglong2 f = ldp(&sf[4 * c4]);
            ffma2(a, w.x, f.x);
            ffma2(a, w.y, f.y);
        }
    } else {
        const int d = t - GP_GK;
        #pragma unroll
        for (int c4 = 0; c4 < 16; c4++) {
            const ulonglong2 w = ldp(&Wkgp[c4 * DIMK + d]);
            const ulonglong2 f = ldp(&sf[4 * c4]);
            ffma2(a, w.x, f.x);
            ffma2(a, w.y, f.y);
        }
    }
    g_GP[(size_t)pt * GPW + t] = hsum2(a);
}

// ---------------------------------------------------------------------------
// Kernel 1: brute-force KNN; per-lane top-2 cache, rare rescans
// ---------------------------------------------------------------------------
__global__ void knn_kernel(const float* __restrict__ x)
{
    extern __shared__ float sm[];
    float* sx   = sm;
    float* sy   = sx + NN;
    float* sz   = sy + NN;
    float* ss   = sz + NN;
    float* dist = ss + NN;      // [8][NN]

    const int b     = blockIdx.x >> 8;
    const int qbase = (blockIdx.x & 255) << 3;
    const int t     = threadIdx.x;
    const int w     = t >> 5;
    const int lane  = t & 31;

    for (int j = t; j < NN; j += 256) {
        const float* p = x + ((size_t)b * NN + j) * CIN;
        float a0 = p[0], a1 = p[1], a2 = p[2];
        sx[j] = a0; sy[j] = a1; sz[j] = a2;
        ss[j] = a0 * a0 + a1 * a1 + a2 * a2;
    }
    __syncthreads();

    const int n = qbase + w;
    const float qx = sx[n], qy = sy[n], qz = sz[n], sq = ss[n];
    float* dw = dist + w * NN;

    float v1 = FLT_MAX, v2 = FLT_MAX;
    int   i1 = 0x7fffffff, i2 = 0x7fffffff;
    for (int j = lane; j < NN; j += 32) {
        const float dot = qx * sx[j] + qy * sy[j] + qz * sz[j];
        const float d   = -2.0f * dot + sq + ss[j];
        dw[j] = d;
        if (d < v1)      { v2 = v1; i2 = i1; v1 = d; i1 = j; }
        else if (d < v2) { v2 = d;  i2 = j; }
    }
    __syncwarp();

    for (int sel = 0; sel < KNNK; sel++) {
        float wv = v1;
        int   wi = i1;
        #pragma unroll
        for (int o = 16; o; o >>= 1) {
            float ov = __shfl_xor_sync(0xffffffffu, wv, o);
            int   oi = __shfl_xor_sync(0xffffffffu, wi, o);
            if (ov < wv || (ov == wv && oi < wi)) { wv = ov; wi = oi; }
        }
        if (lane == 0)
            g_idx[((size_t)b * NN + n) * KNNK + sel] = wi;
        if (i1 == wi) {
            dw[wi] = FLT_MAX;
            v1 = v2; i1 = i2;
            v2 = FLT_MAX; i2 = 0x7fffffff;
            if (v1 == FLT_MAX) {
                for (int j = lane; j < NN; j += 32) {
                    const float d = dw[j];
                    if (d < v1)      { v2 = v1; i2 = i1; v1 = d; i1 = j; }
                    else if (d < v2) { v2 = d;  i2 = j; }
                }
            }
        }
        __syncwarp();
    }
}

// ---------------------------------------------------------------------------
// fused block reduction: component-wise sum of float4 over 128 threads
// ---------------------------------------------------------------------------
__device__ __forceinline__ float4 block_sum4_128(float4 v, float4* sred, float4* sbc)
{
    #pragma unroll
    for (int o = 16; o; o >>= 1) {
        v.x += __shfl_xor_sync(0xffffffffu, v.x, o);
        v.y += __shfl_xor_sync(0xffffffffu, v.y, o);
        v.z += __shfl_xor_sync(0xffffffffu, v.z, o);
        v.w += __shfl_xor_sync(0xffffffffu, v.w, o);
    }
    if ((threadIdx.x & 31) == 0) sred[threadIdx.x >> 5] = v;
    __syncthreads();
    if (threadIdx.x == 0) {
        float4 a = sred[0], b = sred[1], c = sred[2], d = sred[3];
        *sbc = make_float4(a.x + b.x + c.x + d.x, a.y + b.y + c.y + d.y,
                           a.z + b.z + c.z + d.z, a.w + b.w + c.w + d.w);
    }
    __syncthreads();
    return *sbc;
}

// ---------------------------------------------------------------------------
// Kernel 2: fused block, TWO points per block, gathered per-point transforms.
// ---------------------------------------------------------------------------
__global__ void __launch_bounds__(128)
fused_kernel(const float* __restrict__ x,
             const float* __restrict__ Wh,
             const float* __restrict__ g1, const float* __restrict__ b1,
             const float* __restrict__ g2, const float* __restrict__ b2,
             const float* __restrict__ lnqw, const float* __restrict__ lnqb,
             const float* __restrict__ lnvw, const float* __restrict__ lnvb,
             const float* __restrict__ lnow, const float* __restrict__ lnob,
             float* __restrict__ out)
{
    const int bn0 = blockIdx.x << 1;
    const int b   = bn0 >> 11;
    const int n0  = bn0 & (NN - 1);
    const int t   = threadIdx.x;

    __shared__ __align__(16) float sGP [2][KNNK * GPW];   // gathered transforms
    __shared__ __align__(16) float sPos[2][KNNK * DIMV];  // pos features
    __shared__ __align__(16) float sH1[2][KNNK * CH];
    __shared__ __align__(16) float sPM[2][2 * CH];
    __shared__ __align__(16) float sFQ[2][CH];
    __shared__ __align__(16) float sQ [2][NHEAD * DIMK];
    __shared__ __align__(16) float sV [2][KNNK * DIMV];
    __shared__ __align__(16) float sKK[2][KNNK * DIMK];
    __shared__ __align__(16) float sKV[2][DIMK * DIMV];
    __shared__ __align__(16) float sCF[2][CFE];
    __shared__ __align__(16) float sC1[2][CH];
    __shared__ __align__(16) float sCV[2][DIMV];
    __shared__ int    sIdx[2][KNNK];
    __shared__ float4 sred[4];
    __shared__ float4 sbc[1];

    const float* xb  = x + (size_t)b * NN * CIN;
    const float* xc0 = xb + (size_t)n0 * CIN;
    const float* xc1 = xc0 + CIN;

    if (t < 6) {
        const int p = t / 3, c = t - 3 * p;
        out[(size_t)(bn0 + p) * 3 + c] = (p ? xc1 : xc0)[c];
    }
    {
        const int p = t >> 6, c = t & 63;
        sCF[p][c] = (p ? xc1 : xc0)[3 + c];
    }
    if (t < 2 * KNNK) {
        const int p = t / KNNK, kk = t - p * KNNK;
        sIdx[p][kk] = g_idx[(size_t)(bn0 + p) * KNNK + kk];
    }
    __syncthreads();

    // ---- per-point constants (center-folded) -----------------------------------
    {
        const int p = t >> 6, oo = t & 63;
        ull a = 0ull;
        #pragma unroll
        for (int c4 = 0; c4 < CFE / 4; c4++) {
            const ulonglong2 w = ldp(&W1dp[c4 * CH + oo]);
            const ulonglong2 f = ldp(&sCF[p][4 * c4]);
            ffma2(a, w.x, f.x);
            ffma2(a, w.y, f.y);
        }
        sC1[p][oo] = hsum2(a);
    }
    if (t < 32) {
        const int p = t >> 4, vd = t & 15;
        ull a = 0ull;
        #pragma unroll
        for (int c4 = 0; c4 < CFE / 4; c4++) {
            const ulonglong2 w = ldp(&Wvdp[c4 * DIMV + vd]);
            const ulonglong2 f = ldp(&sCF[p][4 * c4]);
            ffma2(a, w.x, f.x);
            ffma2(a, w.y, f.y);
        }
        sCV[p][vd] = hsum2(a);
    }

    // ---- gather per-neighbor transforms (28 float4 per neighbor) ----------------
    for (int i = t; i < 2 * KNNK * (GPW / 4); i += 128) {
        const int p = i / (KNNK * (GPW / 4));
        const int r = i - p * (KNNK * (GPW / 4));
        const int k = r / (GPW / 4), q = r - k * (GPW / 4);
        const float4 v = *(const float4*)
            &g_GP[((size_t)(b * NN + sIdx[p][k])) * GPW + 4 * q];
        *(float4*)&sGP[p][k * GPW + 4 * q] = v;
    }

    // ---- pos features -------------------------------------------------------------
    {
        const float c0x = xc0[0], c0y = xc0[1], c0z = xc0[2];
        const float c1x = xc1[0], c1y = xc1[1], c1z = xc1[2];
        for (int i = t; i < 2 * KNNK * DIMV; i += 128) {
            const int p = i / (KNNK * DIMV);
            const int r = i - p * (KNNK * DIMV);
            const int k = r >> 4, vd = r & 15;
            const float* np = xb + (size_t)sIdx[p][k] * CIN;
            const float rx = np[0] - (p ? c1x : c0x);
            const float ry = np[1] - (p ? c1y : c0y);
            const float rz = np[2] - (p ? c1z : c0z);
            sPos[p][k * DIMV + vd] =
                Wh[vd * 3 + 0] * rx + Wh[vd * 3 + 1] * ry + Wh[vd * 3 + 2] * rz;
        }
    }
    __syncthreads();

    const float bn_rs = rsqrtf(1.0f + EPSF);
    const int o  = t & 63;
    const int kg = t >> 6;

    // ---- GEMM1 (pos-only, 16 ch) + gathered feat term -----------------------------
    {
        ull a0[10], a1[10];
        #pragma unroll
        for (int j = 0; j < 10; j++) { a0[j] = 0ull; a1[j] = 0ull; }
        #pragma unroll
        for (int c4 = 0; c4 < 4; c4++) {
            const ulonglong2 w = ldp(&W1gp[(16 + c4) * CH + o]);
            #pragma unroll
            for (int j = 0; j < 10; j++) {
                const ulonglong2 f0 = ldp(&sPos[0][(kg + 2 * j) * DIMV + 4 * c4]);
                ffma2(a0[j], w.x, f0.x);  ffma2(a0[j], w.y, f0.y);
                const ulonglong2 f1 = ldp(&sPos[1][(kg + 2 * j) * DIMV + 4 * c4]);
                ffma2(a1[j], w.x, f1.x);  ffma2(a1[j], w.y, f1.y);
            }
        }
        const float c10 = sC1[0][o], c11 = sC1[1][o];
        const float sc  = g1[o] * bn_rs;
        const float bo  = b1[o];
        #pragma unroll
        for (int j = 0; j < 10; j++) {
            const int k = kg + 2 * j;
            const float h0 = hsum2(a0[j]) + sGP[0][k * GPW + GP_G1 + o] + c10;
            const float h1 = hsum2(a1[j]) + sGP[1][k * GPW + GP_G1 + o] + c11;
            sH1[0][k * CH + o] = fmaxf(h0 * sc + bo, 0.f);
            sH1[1][k * CH + o] = fmaxf(h1 * sc + bo, 0.f);
        }
    }
    if (kg == 0) asm volatile("bar.sync 1, 64;" ::: "memory");
    else         asm volatile("bar.sync 2, 64;" ::: "memory");

    // ---- GEMM2 both points + fold relu/max over k -----------------------------------
    {
        ull a0[10], a1[10];
        #pragma unroll
        for (int j = 0; j < 10; j++) { a0[j] = 0ull; a1[j] = 0ull; }
        #pragma unroll 2
        for (int c4 = 0; c4 < CH / 4; c4++) {
            const ulonglong2 w = ldp(&W2p[c4 * CH + o]);
            #pragma unroll
            for (int j = 0; j < 10; j++) {
                const ulonglong2 f0 = ldp(&sH1[0][(kg + 2 * j) * CH + 4 * c4]);
                ffma2(a0[j], w.x, f0.x);  ffma2(a0[j], w.y, f0.y);
                const ulonglong2 f1 = ldp(&sH1[1][(kg + 2 * j) * CH + 4 * c4]);
                ffma2(a1[j], w.x, f1.x);  ffma2(a1[j], w.y, f1.y);
            }
        }
        const float sc = g2[o] * bn_rs;
        const float bo = b2[o];
        float pm0 = 0.f, pm1 = 0.f;
        #pragma unroll
        for (int j = 0; j < 10; j++) {
            pm0 = fmaxf(pm0, hsum2(a0[j]) * sc + bo);
            pm1 = fmaxf(pm1, hsum2(a1[j]) * sc + bo);
        }
        sPM[0][kg * CH + o] = pm0;
        sPM[1][kg * CH + o] = pm1;
    }
    __syncthreads();

    {
        const int p = t >> 6, oo = t & 63;
        sFQ[p][oo] = fmaxf(sPM[p][oo], sPM[p][CH + oo]);
    }
    __syncthreads();

    // ---- q = relu(LN_256(Wq @ fq)) both points ----------------------------------------
    {
        float qv0[2], qv1[2];
        #pragma unroll
        for (int r = 0; r < 2; r++) {
            const int oq = t + r * 128;
            ull aA = 0ull, aB = 0ull;
            #pragma unroll
            for (int c4 = 0; c4 < CH / 4; c4++) {
                const ulonglong2 w  = ldp(&Wqp[c4 * 256 + oq]);
                const ulonglong2 fA = ldp(&sFQ[0][4 * c4]);
                const ulonglong2 fB = ldp(&sFQ[1][4 * c4]);
                ffma2(aA, w.x, fA.x);  ffma2(aA, w.y, fA.y);
                ffma2(aB, w.x, fB.x);  ffma2(aB, w.y, fB.y);
            }
            qv0[r] = hsum2(aA);
            qv1[r] = hsum2(aB);
        }
        const float4 ssq = block_sum4_128(
            make_float4(qv0[0] + qv0[1], qv0[0] * qv0[0] + qv0[1] * qv0[1],
                        qv1[0] + qv1[1], qv1[0] * qv1[0] + qv1[1] * qv1[1]),
            sred, sbc);
        const float m0 = ssq.x * (1.f / 256.f);
        const float i0 = rsqrtf(ssq.y * (1.f / 256.f) - m0 * m0 + EPSF);
        const float m1 = ssq.z * (1.f / 256.f);
        const float i1 = rsqrtf(ssq.w * (1.f / 256.f) - m1 * m1 + EPSF);
        #pragma unroll
        for (int r = 0; r < 2; r++) {
            const int oq = t + r * 128;
            const float lw = lnqw[oq], lb = lnqb[oq];
            sQ[0][oq] = fmaxf((qv0[r] - m0) * i0 * lw + lb, 0.f);
            sQ[1][oq] = fmaxf((qv1[r] - m1) * i1 * lw + lb, 0.f);
        }
    }

    // ---- v-raw (pos-only + gather): vd = t&15, k0 = t>>4 --------------------------------
    {
        const int vd = t & 15;
        const int k0 = t >> 4;
        ull p0a = 0ull, p0b = 0ull, p0c = 0ull;
        ull p1a = 0ull, p1b = 0ull, p1c = 0ull;
        const bool has2 = (k0 < 4);
        #pragma unroll
        for (int c4 = 0; c4 < 4; c4++) {
            const ulonglong2 w = ldp(&Wvgp[(16 + c4) * DIMV + vd]);
            {
                const ulonglong2 f0 = ldp(&sPos[0][k0 * DIMV + 4 * c4]);
                const ulonglong2 f1 = ldp(&sPos[0][(k0 + 8) * DIMV + 4 * c4]);
                ffma2(p0a, w.x, f0.x);  ffma2(p0a, w.y, f0.y);
                ffma2(p0b, w.x, f1.x);  ffma2(p0b, w.y, f1.y);
                if (has2) {
                    const ulonglong2 f2 = ldp(&sPos[0][(k0 + 16) * DIMV + 4 * c4]);
                    ffma2(p0c, w.x, f2.x);  ffma2(p0c, w.y, f2.y);
                }
            }
            {
                const ulonglong2 f0 = ldp(&sPos[1][k0 * DIMV + 4 * c4]);
                const ulonglong2 f1 = ldp(&sPos[1][(k0 + 8) * DIMV + 4 * c4]);
                ffma2(p1a, w.x, f0.x);  ffma2(p1a, w.y, f0.y);
                ffma2(p1b, w.x, f1.x);  ffma2(p1b, w.y, f1.y);
                if (has2) {
                    const ulonglong2 f2 = ldp(&sPos[1][(k0 + 16) * DIMV + 4 * c4]);
                    ffma2(p1c, w.x, f2.x);  ffma2(p1c, w.y, f2.y);
                }
            }
        }
        const float cv0 = sCV[0][vd], cv1 = sCV[1][vd];
        sV[0][k0 * DIMV + vd]       = hsum2(p0a) + sGP[0][k0 * GPW + GP_GV + vd] + cv0;
        sV[0][(k0 + 8) * DIMV + vd] = hsum2(p0b) + sGP[0][(k0 + 8) * GPW + GP_GV + vd] + cv0;
        sV[1][k0 * DIMV + vd]       = hsum2(p1a) + sGP[1][k0 * GPW + GP_GV + vd] + cv1;
        sV[1][(k0 + 8) * DIMV + vd] = hsum2(p1b) + sGP[1][(k0 + 8) * GPW + GP_GV + vd] + cv1;
        if (has2) {
            sV[0][(k0 + 16) * DIMV + vd] = hsum2(p0c) + sGP[0][(k0 + 16) * GPW + GP_GV + vd] + cv0;
            sV[1][(k0 + 16) * DIMV + vd] = hsum2(p1c) + sGP[1][(k0 + 16) * GPW + GP_GV + vd] + cv1;
        }
    }

    // ---- kk-raw (pos-only + gather): d = t&31, kb = t>>5, 5 k each ------------------------
    {
        const int d  = t & 31;
        const int kb = t >> 5;
        ull a0[5], a1[5];
        #pragma unroll
        for (int p = 0; p < 5; p++) { a0[p] = 0ull; a1[p] = 0ull; }
        #pragma unroll
        for (int c4 = 0; c4 < 4; c4++) {
            const ulonglong2 w = ldp(&Wkgp[(16 + c4) * DIMK + d]);
            #pragma unroll
            for (int p = 0; p < 5; p++) {
                const ulonglong2 f0 = ldp(&sPos[0][(kb + 4 * p) * DIMV + 4 * c4]);
                ffma2(a0[p], w.x, f0.x);  ffma2(a0[p], w.y, f0.y);
                const ulonglong2 f1 = ldp(&sPos[1][(kb + 4 * p) * DIMV + 4 * c4]);
                ffma2(a1[p], w.x, f1.x);  ffma2(a1[p], w.y, f1.y);
            }
        }
        #pragma unroll
        for (int p = 0; p < 5; p++) {
            const int k = kb + 4 * p;
            sKK[0][k * DIMK + d] = hsum2(a0[p]) + sGP[0][k * GPW + GP_GK + d];
            sKK[1][k * DIMK + d] = hsum2(a1[p]) + sGP[1][k * GPW + GP_GK + d];
        }
    }
    __syncthreads();

    // ---- LN_16 over v (threads 0-39) || softmax over k (threads 64-127) -------------------
    if (t < 2 * KNNK) {
        const int p = t / KNNK, row = t - p * KNNK;
        float s = 0.f, s2 = 0.f;
        #pragma unroll
        for (int vd = 0; vd < DIMV; vd++) {
            const float v = sV[p][row * DIMV + vd];
            s += v; s2 += v * v;
        }
        const float m   = s * (1.f / DIMV);
        const float var = s2 * (1.f / DIMV) - m * m;
        const float inv = rsqrtf(var + EPSF);
        #pragma unroll
        for (int vd = 0; vd < DIMV; vd++)
            sV[p][row * DIMV + vd] =
                (sV[p][row * DIMV + vd] - m) * inv * lnvw[vd] + lnvb[vd];
    } else if (t >= 64) {
        const int idx = t - 64;
        const int p = idx >> 5, d = idx & 31;
        float mx = -FLT_MAX;
        #pragma unroll
        for (int k = 0; k < KNNK; k++) mx = fmaxf(mx, sKK[p][k * DIMK + d]);
        float sum = 0.f;
        #pragma unroll
        for (int k = 0; k < KNNK; k++) {
            const float e = expf(sKK[p][k * DIMK + d] - mx);
            sKK[p][k * DIMK + d] = e;
            sum += e;
        }
        const float inv = 1.f / sum;
        #pragma unroll
        for (int k = 0; k < KNNK; k++) sKK[p][k * DIMK + d] *= inv;
    }
    __syncthreads();

    // ---- kv[p][d][v] = sum_k kk[k][d] * v[k][v] -----------------------------------------
    for (int i = t; i < 2 * DIMK * DIMV; i += 128) {
        const int p = i >> 9;
        const int r = i & 511;
        const int d = r >> 4, vd = r & 15;
        float acc = 0.f;
        #pragma unroll
        for (int k = 0; k < KNNK; k++)
            acc += sKK[p][k * DIMK + d] * sV[p][k * DIMV + vd];
        sKV[p][r] = acc;
    }
    __syncthreads();

    // ---- out = LN_128(q @ kv) both points, write transposed --------------------------------
    {
        const int h = t >> 4, vd = t & 15;
        float acc0 = 0.f, acc1 = 0.f;
        #pragma unroll
        for (int d = 0; d < DIMK; d++) {
            acc0 += sQ[0][h * DIMK + d] * sKV[0][d * DIMV + vd];
            acc1 += sQ[1][h * DIMK + d] * sKV[1][d * DIMV + vd];
        }
        const float4 ssq = block_sum4_128(
            make_float4(acc0, acc0 * acc0, acc1, acc1 * acc1), sred, sbc);
        const float m0 = ssq.x * (1.f / COUT);
        const float i0 = rsqrtf(ssq.y * (1.f / COUT) - m0 * m0 + EPSF);
        const float m1 = ssq.z * (1.f / COUT);
        const float i1 = rsqrtf(ssq.w * (1.f / COUT) - m1 * m1 + EPSF);
        const float lw = lnow[t], lb = lnob[t];
        float* op = out + XYZ_TOT + ((size_t)b * COUT + t) * NN + n0;
        op[0] = (acc0 - m0) * i0 * lw + lb;
        op[1] = (acc1 - m1) * i1 * lw + lb;
    }
}

// ---------------------------------------------------------------------------
// launch
// ---------------------------------------------------------------------------
extern "C" void kernel_launch(void* const* d_in, const int* in_sizes, int n_in,
                              void* d_out, int out_size)
{
    const float* x    = (const float*)d_in[0];
    const float* Wh   = (const float*)d_in[1];
    const float* W1   = (const float*)d_in[2];
    const float* g1   = (const float*)d_in[3];
    const float* b1   = (const float*)d_in[4];
    const float* W2   = (const float*)d_in[5];
    const float* g2   = (const float*)d_in[6];
    const float* b2   = (const float*)d_in[7];
    const float* Wq   = (const float*)d_in[8];
    const float* lnqw = (const float*)d_in[9];
    const float* lnqb = (const float*)d_in[10];
    const float* Wv   = (const float*)d_in[11];
    const float* lnvw = (const float*)d_in[12];
    const float* lnvb = (const float*)d_in[13];
    const float* Wk   = (const float*)d_in[14];
    const float* lnow = (const float*)d_in[15];
    const float* lnob = (const float*)d_in[16];
    float* out = (float*)d_out;

    const int pack_total = (CR/4)*CH + (CFE/4)*CH + (CH/4)*CH + (CH/4)*NHEAD*DIMK
                         + (CR/4)*DIMV + (CFE/4)*DIMV + (CR/4)*DIMK;
    pack_weights<<<(pack_total + 127) / 128, 128>>>(W1, W2, Wq, Wv, Wk);

    // per-point feat transforms (needs packed weights)
    precompute_points<<<BB * NN, 128>>>(x);

    const int knn_smem = (4 * NN + 8 * NN) * (int)sizeof(float);  // 96 KB
    cudaFuncSetAttribute(knn_kernel,
                         cudaFuncAttributeMaxDynamicSharedMemorySize, knn_smem);
    knn_kernel<<<BB * (NN / 8), 256, knn_smem>>>(x);

    fused_kernel<<<BB * NN / 2, 128>>>(x, Wh,
                                       g1, b1, g2, b2,
                                       lnqw, lnqb, lnvw, lnvb,
                                       lnow, lnob,
                                       out);
}

// round 16
// speedup vs baseline: 1.9110x; 1.0543x over previous
#include <cuda_runtime.h>
#include <float.h>
#include <math.h>

// ---------------------------------------------------------------------------
// Problem constants
// ---------------------------------------------------------------------------
#define BB    8
#define NN    2048
#define KNNK  20
#define CIN   67          // 3 xyz + 64 feat
#define CFE   64
#define CCC   144         // 64 gpn + 64 center + 16 pos
#define CR    80
#define CH    64
#define DIMV  16
#define DIMK  32
#define NHEAD 8
#define COUT  128
#define EPSF  1e-5f
#define XYZ_TOT (BB*NN*3)
#define GPW   128         // padded per-point transform row in GLOBAL (floats)
#define GPS   112         // per-point transform row in SHARED (floats)
#define GP_G1 0
#define GP_GV 64
#define GP_GK 80

typedef unsigned long long ull;

// scratch (no allocation allowed -> __device__ globals)
__device__ int    g_idx[BB * NN * KNNK];
__device__ float4 W1gp[(CR/4) * CH];            // [c4 0..19][o]  (c4<16: feat, >=16: pos)
__device__ float4 W1dp[(CFE/4) * CH];           // center-fold diff for W1
__device__ float4 W2p [(CH/4)  * CH];
__device__ float4 Wqp [(CH/4)  * (NHEAD*DIMK)];
__device__ float4 Wvgp[(CR/4) * DIMV];
__device__ float4 Wvdp[(CFE/4) * DIMV];
__device__ float4 Wkgp[(CR/4) * DIMK];
__device__ float4 g_GP4[BB * NN * (GPW/4)];     // padded per-point feat transforms
__device__ float  g_C1V[BB * NN * 80];          // per-point center-fold consts
__device__ float4 g_XYZS[BB * NN];              // packed (x, y, z, |p|^2)

// ---------------------------------------------------------------------------
// packed dual-fp32 FMA helpers
// ---------------------------------------------------------------------------
__device__ __forceinline__ void ffma2(ull& d, ull a, ull b)
{
    asm("fma.rn.f32x2 %0, %1, %2, %0;" : "+l"(d) : "l"(a), "l"(b));
}
__device__ __forceinline__ float hsum2(ull v)
{
    float lo, hi;
    asm("mov.b64 {%0, %1}, %2;" : "=f"(lo), "=f"(hi) : "l"(v));
    return lo + hi;
}
__device__ __forceinline__ ulonglong2 ldp(const void* p)
{
    return *(const ulonglong2*)p;
}

// ---------------------------------------------------------------------------
// Kernel 0: pack weights (transposed + center-folded layouts)
// ---------------------------------------------------------------------------
__global__ void pack_weights(const float* __restrict__ W1, const float* __restrict__ W2,
                             const float* __restrict__ Wq, const float* __restrict__ Wv,
                             const float* __restrict__ Wk)
{
    int i = blockIdx.x * blockDim.x + threadIdx.x;

    if (i < (CR/4)*CH) {
        int c4 = i >> 6, o = i & 63;
        int col = (c4 < 16) ? 4 * c4 : 128 + 4 * (c4 - 16);
        W1gp[i] = *(const float4*)&W1[o * CCC + col];
        return;
    }
    i -= (CR/4)*CH;
    if (i < (CFE/4)*CH) {
        int c4 = i >> 6, o = i & 63;
        float4 a = *(const float4*)&W1[o * CCC + 64 + 4 * c4];
        float4 b = *(const float4*)&W1[o * CCC + 4 * c4];
        W1dp[i] = make_float4(a.x - b.x, a.y - b.y, a.z - b.z, a.w - b.w);
        return;
    }
    i -= (CFE/4)*CH;
    if (i < (CH/4)*CH) {
        int c4 = i >> 6, o = i & 63;
        W2p[i] = *(const float4*)&W2[o * CH + 4 * c4];
        return;
    }
    i -= (CH/4)*CH;
    if (i < (CH/4)*NHEAD*DIMK) {
        int c4 = i >> 8, o = i & 255;
        Wqp[i] = *(const float4*)&Wq[o * CH + 4 * c4];
        return;
    }
    i -= (CH/4)*NHEAD*DIMK;
    if (i < (CR/4)*DIMV) {
        int c4 = i >> 4, vd = i & 15;
        int col = (c4 < 16) ? 4 * c4 : 128 + 4 * (c4 - 16);
        Wvgp[i] = *(const float4*)&Wv[vd * CCC + col];
        return;
    }
    i -= (CR/4)*DIMV;
    if (i < (CFE/4)*DIMV) {
        int c4 = i >> 4, vd = i & 15;
        float4 a = *(const float4*)&Wv[vd * CCC + 64 + 4 * c4];
        float4 b = *(const float4*)&Wv[vd * CCC + 4 * c4];
        Wvdp[i] = make_float4(a.x - b.x, a.y - b.y, a.z - b.z, a.w - b.w);
        return;
    }
    i -= (CFE/4)*DIMV;
    if (i < (CR/4)*DIMK) {
        int c4 = i >> 5, d = i & 31;
        int col = (c4 < 16) ? 4 * c4 : 128 + 4 * (c4 - 16);
        Wkgp[i] = *(const float4*)&Wk[d * CCC + col];
    }
}

// ---------------------------------------------------------------------------
// Kernel 0b: per-point precompute.
//   g_GP4 row (128 floats): [0:64)=W1f@feat, [64:80)=Wvf@feat, [80:112)=Wkf@feat
//   g_C1V row (80 floats):  [0:64)=C1, [64:80)=CV
//   g_XYZS: packed (x,y,z,|p|^2)
// ---------------------------------------------------------------------------
__global__ void __launch_bounds__(128)
precompute_points(const float* __restrict__ x)
{
    const int pt = blockIdx.x;
    const int t  = threadIdx.x;
    __shared__ __align__(16) float sf[CFE];

    const float* xc = x + (size_t)pt * CIN;
    if (t < CFE) sf[t] = xc[3 + t];
    __syncthreads();

    float* gp = (float*)g_GP4 + (size_t)pt * GPW;

    if (t < 112) {
        ull a = 0ull;
        if (t < GP_GV) {
            #pragma unroll
            for (int c4 = 0; c4 < 16; c4++) {
                const ulonglong2 w = ldp(&W1gp[c4 * CH + t]);
                const ulonglong2 f = ldp(&sf[4 * c4]);
                ffma2(a, w.x, f.x);
                ffma2(a, w.y, f.y);
            }
        } else if (t < GP_GK) {
            const int vd = t - GP_GV;
            #pragma unroll
            for (int c4 = 0; c4 < 16; c4++) {
                const ulonglong2 w = ldp(&Wvgp[c4 * DIMV + vd]);
                const ulonglong2 f = ldp(&sf[4 * c4]);
                ffma2(a, w.x, f.x);
                ffma2(a, w.y, f.y);
            }
        } else {
            const int d = t - GP_GK;
            #pragma unroll
            for (int c4 = 0; c4 < 16; c4++) {
                const ulonglong2 w = ldp(&Wkgp[c4 * DIMK + d]);
                const ulonglong2 f = ldp(&sf[4 * c4]);
                ffma2(a, w.x, f.x);
                ffma2(a, w.y, f.y);
            }
        }
        gp[t] = hsum2(a);
    } else {
        gp[t] = 0.f;   // pad
        if (t == 127) {
            const float a0 = xc[0], a1 = xc[1], a2 = xc[2];
            g_XYZS[pt] = make_float4(a0, a1, a2, a0 * a0 + a1 * a1 + a2 * a2);
        }
    }

    // pass 2: center-fold constants
    if (t < CFE) {
        ull a = 0ull;
        #pragma unroll
        for (int c4 = 0; c4 < 16; c4++) {
            const ulonglong2 w = ldp(&W1dp[c4 * CH + t]);
            const ulonglong2 f = ldp(&sf[4 * c4]);
            ffma2(a, w.x, f.x);
            ffma2(a, w.y, f.y);
        }
        g_C1V[(size_t)pt * 80 + t] = hsum2(a);
    } else if (t < 80) {
        const int vd = t - CFE;
        ull a = 0ull;
        #pragma unroll
        for (int c4 = 0; c4 < 16; c4++) {
            const ulonglong2 w = ldp(&Wvdp[c4 * DIMV + vd]);
            const ulonglong2 f = ldp(&sf[4 * c4]);
            ffma2(a, w.x, f.x);
            ffma2(a, w.y, f.y);
        }
        g_C1V[(size_t)pt * 80 + t] = hsum2(a);
    }
}

// ---------------------------------------------------------------------------
// Kernel 1: brute-force KNN with packed float4 xyz; top-2 cache selection
// ---------------------------------------------------------------------------
__global__ void knn_kernel()
{
    extern __shared__ float sm[];
    float4* sP   = (float4*)sm;        // [NN] packed (x,y,z,ss)
    float*  dist = sm + 4 * NN;        // [8][NN]

    const int b     = blockIdx.x >> 8;
    const int qbase = (blockIdx.x & 255) << 3;
    const int t     = threadIdx.x;
    const int w     = t >> 5;
    const int lane  = t & 31;

    for (int j = t; j < NN; j += 256)
        sP[j] = g_XYZS[b * NN + j];
    __syncthreads();

    const int n = qbase + w;
    const float4 q4 = sP[n];
    float* dw = dist + w * NN;

    float v1 = FLT_MAX, v2 = FLT_MAX;
    int   i1 = 0x7fffffff, i2 = 0x7fffffff;
    for (int j = lane; j < NN; j += 32) {
        const float4 v = sP[j];
        const float dot = q4.x * v.x + q4.y * v.y + q4.z * v.z;
        const float d   = -2.0f * dot + q4.w + v.w;
        dw[j] = d;
        if (d < v1)      { v2 = v1; i2 = i1; v1 = d; i1 = j; }
        else if (d < v2) { v2 = d;  i2 = j; }
    }
    __syncwarp();

    for (int sel = 0; sel < KNNK; sel++) {
        float wv = v1;
        int   wi = i1;
        #pragma unroll
        for (int o = 16; o; o >>= 1) {
            float ov = __shfl_xor_sync(0xffffffffu, wv, o);
            int   oi = __shfl_xor_sync(0xffffffffu, wi, o);
            if (ov < wv || (ov == wv && oi < wi)) { wv = ov; wi = oi; }
        }
        if (lane == 0)
            g_idx[((size_t)b * NN + n) * KNNK + sel] = wi;
        if (i1 == wi) {
            dw[wi] = FLT_MAX;
            v1 = v2; i1 = i2;
            v2 = FLT_MAX; i2 = 0x7fffffff;
            if (v1 == FLT_MAX) {
                for (int j = lane; j < NN; j += 32) {
                    const float d = dw[j];
                    if (d < v1)      { v2 = v1; i2 = i1; v1 = d; i1 = j; }
                    else if (d < v2) { v2 = d;  i2 = j; }
                }
            }
        }
        __syncwarp();
    }
}

// ---------------------------------------------------------------------------
// fused block reduction: component-wise sum of float4 over 128 threads
// ---------------------------------------------------------------------------
__device__ __forceinline__ float4 block_sum4_128(float4 v, float4* sred, float4* sbc)
{
    #pragma unroll
    for (int o = 16; o; o >>= 1) {
        v.x += __shfl_xor_sync(0xffffffffu, v.x, o);
        v.y += __shfl_xor_sync(0xffffffffu, v.y, o);
        v.z += __shfl_xor_sync(0xffffffffu, v.z, o);
        v.w += __shfl_xor_sync(0xffffffffu, v.w, o);
    }
    if ((threadIdx.x & 31) == 0) sred[threadIdx.x >> 5] = v;
    __syncthreads();
    if (threadIdx.x == 0) {
        float4 a = sred[0], b = sred[1], c = sred[2], d = sred[3];
        *sbc = make_float4(a.x + b.x + c.x + d.x, a.y + b.y + c.y + d.y,
                           a.z + b.z + c.z + d.z, a.w + b.w + c.w + d.w);
    }
    __syncthreads();
    return *sbc;
}

// ---------------------------------------------------------------------------
// Kernel 2: fused block, TWO points per block, o-paired GEMM mapping.
// ---------------------------------------------------------------------------
__global__ void __launch_bounds__(128)
fused_kernel(const float* __restrict__ Wh,
             const float* __restrict__ g1, const float* __restrict__ b1,
             const float* __restrict__ g2, const float* __restrict__ b2,
             const float* __restrict__ lnqw, const float* __restrict__ lnqb,
             const float* __restrict__ lnvw, const float* __restrict__ lnvb,
             const float* __restrict__ lnow, const float* __restrict__ lnob,
             float* __restrict__ out)
{
    const int bn0 = blockIdx.x << 1;
    const int b   = bn0 >> 11;
    const int n0  = bn0 & (NN - 1);
    const int t   = threadIdx.x;

    __shared__ __align__(16) float sGP [2][KNNK * GPS];   // 2 x 20 x 112
    __shared__ __align__(16) float sPos[2][KNNK * DIMV];
    __shared__ __align__(16) float sH1[2][KNNK * CH];
    __shared__ __align__(16) float sPM[2][4 * CH];
    __shared__ __align__(16) float sFQ[2][CH];
    __shared__ __align__(16) float sQ [2][NHEAD * DIMK];
    __shared__ __align__(16) float sV [2][KNNK * DIMV];
    __shared__ __align__(16) float sKK[2][KNNK * DIMK];
    __shared__ __align__(16) float sKV[2][DIMK * DIMV];
    __shared__ int    sIdx[2][KNNK];
    __shared__ float4 sred[4];
    __shared__ float4 sbc[1];

    if (t < 2 * KNNK) {
        const int p = t / KNNK, kk = t - p * KNNK;
        sIdx[p][kk] = g_idx[(size_t)(bn0 + p) * KNNK + kk];
    }
    if (t < 6) {   // xyz passthrough
        const int p = t / 3, c = t - 3 * p;
        out[(size_t)(bn0 + p) * 3 + c] = ((const float*)&g_XYZS[bn0 + p])[c];
    }
    __syncthreads();

    // ---- gather per-neighbor transforms (28 aligned float4 per neighbor) -------
    #pragma unroll
    for (int p = 0; p < 2; p++) {
        for (int i = t; i < KNNK * (GPS / 4); i += 128) {
            const int k = i / (GPS / 4), q = i - k * (GPS / 4);
            ((float4*)sGP[p])[i] =
                g_GP4[(size_t)(b * NN + sIdx[p][k]) * (GPW / 4) + q];
        }
    }

    // ---- pos features from packed xyz -------------------------------------------
    {
        const float4 cen0 = g_XYZS[bn0];
        const float4 cen1 = g_XYZS[bn0 + 1];
        #pragma unroll
        for (int p = 0; p < 2; p++) {
            const float cx = p ? cen1.x : cen0.x;
            const float cy = p ? cen1.y : cen0.y;
            const float cz = p ? cen1.z : cen0.z;
            for (int i = t; i < KNNK * DIMV; i += 128) {
                const int k = i >> 4, vd = i & 15;
                const float4 nb = g_XYZS[b * NN + sIdx[p][k]];
                const float rx = nb.x - cx, ry = nb.y - cy, rz = nb.z - cz;
                sPos[p][i] =
                    Wh[vd * 3 + 0] * rx + Wh[vd * 3 + 1] * ry + Wh[vd * 3 + 2] * rz;
            }
        }
    }
    __syncthreads();

    const float bn_rs = rsqrtf(1.0f + EPSF);
    const int o1 = t & 31;
    const int o2 = o1 + 32;
    const int wg = t >> 5;            // warp owns rows k = wg + 4j

    // ---- GEMM1 (pos-only 16ch) + gathered feat + C1; o-paired -------------------
    {
        ull acc[2][5][2];
        #pragma unroll
        for (int oi = 0; oi < 2; oi++)
            #pragma unroll
            for (int j = 0; j < 5; j++) { acc[oi][j][0] = 0ull; acc[oi][j][1] = 0ull; }
        #pragma unroll
        for (int c4 = 0; c4 < 4; c4++) {
            const ulonglong2 w1 = ldp(&W1gp[(16 + c4) * CH + o1]);
            const ulonglong2 w2 = ldp(&W1gp[(16 + c4) * CH + o2]);
            #pragma unroll
            for (int j = 0; j < 5; j++) {
                #pragma unroll
                for (int p = 0; p < 2; p++) {
                    const ulonglong2 f = ldp(&sPos[p][(wg + 4 * j) * DIMV + 4 * c4]);
                    ffma2(acc[0][j][p], w1.x, f.x);  ffma2(acc[0][j][p], w1.y, f.y);
                    ffma2(acc[1][j][p], w2.x, f.x);  ffma2(acc[1][j][p], w2.y, f.y);
                }
            }
        }
        const float c1a0 = g_C1V[(size_t)bn0 * 80 + o1];
        const float c1b0 = g_C1V[(size_t)bn0 * 80 + o2];
        const float c1a1 = g_C1V[(size_t)(bn0 + 1) * 80 + o1];
        const float c1b1 = g_C1V[(size_t)(bn0 + 1) * 80 + o2];
        const float sca = g1[o1] * bn_rs, boa = b1[o1];
        const float scb = g1[o2] * bn_rs, bob = b1[o2];
        #pragma unroll
        for (int j = 0; j < 5; j++) {
            const int k = wg + 4 * j;
            #pragma unroll
            for (int p = 0; p < 2; p++) {
                const float ha = hsum2(acc[0][j][p]) + sGP[p][k * GPS + GP_G1 + o1]
                               + (p ? c1a1 : c1a0);
                const float hb = hsum2(acc[1][j][p]) + sGP[p][k * GPS + GP_G1 + o2]
                               + (p ? c1b1 : c1b0);
                sH1[p][k * CH + o1] = fmaxf(ha * sca + boa, 0.f);
                sH1[p][k * CH + o2] = fmaxf(hb * scb + bob, 0.f);
            }
        }
    }
    __syncwarp();   // GEMM1->GEMM2 is warp-private under this mapping

    // ---- GEMM2 + fold relu/max over k; o-paired ----------------------------------
    {
        ull acc[2][5][2];
        #pragma unroll
        for (int oi = 0; oi < 2; oi++)
            #pragma unroll
            for (int j = 0; j < 5; j++) { acc[oi][j][0] = 0ull; acc[oi][j][1] = 0ull; }
        #pragma unroll 2
        for (int c4 = 0; c4 < CH / 4; c4++) {
            const ulonglong2 w1 = ldp(&W2p[c4 * CH + o1]);
            const ulonglong2 w2 = ldp(&W2p[c4 * CH + o2]);
            #pragma unroll
            for (int j = 0; j < 5; j++) {
                #pragma unroll
                for (int p = 0; p < 2; p++) {
                    const ulonglong2 f = ldp(&sH1[p][(wg + 4 * j) * CH + 4 * c4]);
                    ffma2(acc[0][j][p], w1.x, f.x);  ffma2(acc[0][j][p], w1.y, f.y);
                    ffma2(acc[1][j][p], w2.x, f.x);  ffma2(acc[1][j][p], w2.y, f.y);
                }
            }
        }
        const float sca = g2[o1] * bn_rs, boa = b2[o1];
        const float scb = g2[o2] * bn_rs, bob = b2[o2];
        float pma0 = 0.f, pma1 = 0.f, pmb0 = 0.f, pmb1 = 0.f;   // relu floor
        #pragma unroll
        for (int j = 0; j < 5; j++) {
            pma0 = fmaxf(pma0, hsum2(acc[0][j][0]) * sca + boa);
            pma1 = fmaxf(pma1, hsum2(acc[0][j][1]) * sca + boa);
            pmb0 = fmaxf(pmb0, hsum2(acc[1][j][0]) * scb + bob);
            pmb1 = fmaxf(pmb1, hsum2(acc[1][j][1]) * scb + bob);
        }
        sPM[0][wg * CH + o1] = pma0;
        sPM[1][wg * CH + o1] = pma1;
        sPM[0][wg * CH + o2] = pmb0;
        sPM[1][wg * CH + o2] = pmb1;
    }
    __syncthreads();

    {
        const int p = t >> 6, oo = t & 63;
        sFQ[p][oo] = fmaxf(fmaxf(sPM[p][oo], sPM[p][CH + oo]),
                           fmaxf(sPM[p][2 * CH + oo], sPM[p][3 * CH + oo]));
    }
    __syncthreads();

    // ---- q = relu(LN_256(Wq @ fq)) both points ------------------------------------
    {
        float qv0[2], qv1[2];
        #pragma unroll
        for (int r = 0; r < 2; r++) {
            const int oq = t + r * 128;
            ull aA = 0ull, aB = 0ull;
            #pragma unroll
            for (int c4 = 0; c4 < CH / 4; c4++) {
                const ulonglong2 w  = ldp(&Wqp[c4 * 256 + oq]);
                const ulonglong2 fA = ldp(&sFQ[0][4 * c4]);
                const ulonglong2 fB = ldp(&sFQ[1][4 * c4]);
                ffma2(aA, w.x, fA.x);  ffma2(aA, w.y, fA.y);
                ffma2(aB, w.x, fB.x);  ffma2(aB, w.y, fB.y);
            }
            qv0[r] = hsum2(aA);
            qv1[r] = hsum2(aB);
        }
        const float4 ssq = block_sum4_128(
            make_float4(qv0[0] + qv0[1], qv0[0] * qv0[0] + qv0[1] * qv0[1],
                        qv1[0] + qv1[1], qv1[0] * qv1[0] + qv1[1] * qv1[1]),
            sred, sbc);
        const float m0 = ssq.x * (1.f / 256.f);
        const float i0 = rsqrtf(ssq.y * (1.f / 256.f) - m0 * m0 + EPSF);
        const float m1 = ssq.z * (1.f / 256.f);
        const float i1 = rsqrtf(ssq.w * (1.f / 256.f) - m1 * m1 + EPSF);
        #pragma unroll
        for (int r = 0; r < 2; r++) {
            const int oq = t + r * 128;
            const float lw = lnqw[oq], lb = lnqb[oq];
            sQ[0][oq] = fmaxf((qv0[r] - m0) * i0 * lw + lb, 0.f);
            sQ[1][oq] = fmaxf((qv1[r] - m1) * i1 * lw + lb, 0.f);
        }
    }

    // ---- v-raw (pos-only + gather + CV): vd = t&15, k0 = t>>4 ----------------------
    {
        const int vd = t & 15;
        const int k0 = t >> 4;
        ull p0a = 0ull, p0b = 0ull, p0c = 0ull;
        ull p1a = 0ull, p1b = 0ull, p1c = 0ull;
        const bool has2 = (k0 < 4);
        #pragma unroll
        for (int c4 = 0; c4 < 4; c4++) {
            const ulonglong2 w = ldp(&Wvgp[(16 + c4) * DIMV + vd]);
            {
                const ulonglong2 f0 = ldp(&sPos[0][k0 * DIMV + 4 * c4]);
                const ulonglong2 f1 = ldp(&sPos[0][(k0 + 8) * DIMV + 4 * c4]);
                ffma2(p0a, w.x, f0.x);  ffma2(p0a, w.y, f0.y);
                ffma2(p0b, w.x, f1.x);  ffma2(p0b, w.y, f1.y);
                if (has2) {
                    const ulonglong2 f2 = ldp(&sPos[0][(k0 + 16) * DIMV + 4 * c4]);
                    ffma2(p0c, w.x, f2.x);  ffma2(p0c, w.y, f2.y);
                }
            }
            {
                const ulonglong2 f0 = ldp(&sPos[1][k0 * DIMV + 4 * c4]);
                const ulonglong2 f1 = ldp(&sPos[1][(k0 + 8) * DIMV + 4 * c4]);
                ffma2(p1a, w.x, f0.x);  ffma2(p1a, w.y, f0.y);
                ffma2(p1b, w.x, f1.x);  ffma2(p1b, w.y, f1.y);
                if (has2) {
                    const ulonglong2 f2 = ldp(&sPos[1][(k0 + 16) * DIMV + 4 * c4]);
                    ffma2(p1c, w.x, f2.x);  ffma2(p1c, w.y, f2.y);
                }
            }
        }
        const float cv0 = g_C1V[(size_t)bn0 * 80 + 64 + vd];
        const float cv1 = g_C1V[(size_t)(bn0 + 1) * 80 + 64 + vd];
        sV[0][k0 * DIMV + vd]       = hsum2(p0a) + sGP[0][k0 * GPS + GP_GV + vd] + cv0;
        sV[0][(k0 + 8) * DIMV + vd] = hsum2(p0b) + sGP[0][(k0 + 8) * GPS + GP_GV + vd] + cv0;
        sV[1][k0 * DIMV + vd]       = hsum2(p1a) + sGP[1][k0 * GPS + GP_GV + vd] + cv1;
        sV[1][(k0 + 8) * DIMV + vd] = hsum2(p1b) + sGP[1][(k0 + 8) * GPS + GP_GV + vd] + cv1;
        if (has2) {
            sV[0][(k0 + 16) * DIMV + vd] = hsum2(p0c) + sGP[0][(k0 + 16) * GPS + GP_GV + vd] + cv0;
            sV[1][(k0 + 16) * DIMV + vd] = hsum2(p1c) + sGP[1][(k0 + 16) * GPS + GP_GV + vd] + cv1;
        }
    }

    // ---- kk-raw (pos-only + gather): d = t&31, kb = t>>5, 5 k each ------------------
    {
        const int d  = t & 31;
        const int kb = t >> 5;
        ull a0[5], a1[5];
        #pragma unroll
        for (int p = 0; p < 5; p++) { a0[p] = 0ull; a1[p] = 0ull; }
        #pragma unroll
        for (int c4 = 0; c4 < 4; c4++) {
            const ulonglong2 w = ldp(&Wkgp[(16 + c4) * DIMK + d]);
            #pragma unroll
            for (int p = 0; p < 5; p++) {
                const ulonglong2 f0 = ldp(&sPos[0][(kb + 4 * p) * DIMV + 4 * c4]);
                ffma2(a0[p], w.x, f0.x);  ffma2(a0[p], w.y, f0.y);
                const ulonglong2 f1 = ldp(&sPos[1][(kb + 4 * p) * DIMV + 4 * c4]);
                ffma2(a1[p], w.x, f1.x);  ffma2(a1[p], w.y, f1.y);
            }
        }
        #pragma unroll
        for (int p = 0; p < 5; p++) {
            const int k = kb + 4 * p;
            sKK[0][k * DIMK + d] = hsum2(a0[p]) + sGP[0][k * GPS + GP_GK + d];
            sKK[1][k * DIMK + d] = hsum2(a1[p]) + sGP[1][k * GPS + GP_GK + d];
        }
    }
    __syncthreads();

    // ---- LN_16 over v (threads 0-39) || softmax over k (threads 64-127) -------------
    if (t < 2 * KNNK) {
        const int p = t / KNNK, row = t - p * KNNK;
        float s = 0.f, s2 = 0.f;
        #pragma unroll
        for (int vd = 0; vd < DIMV; vd++) {
            const float v = sV[p][row * DIMV + vd];
            s += v; s2 += v * v;
        }
        const float m   = s * (1.f / DIMV);
        const float var = s2 * (1.f / DIMV) - m * m;
        const float inv = rsqrtf(var + EPSF);
        #pragma unroll
        for (int vd = 0; vd < DIMV; vd++)
            sV[p][row * DIMV + vd] =
                (sV[p][row * DIMV + vd] - m) * inv * lnvw[vd] + lnvb[vd];
    } else if (t >= 64) {
        const int idx = t - 64;
        const int p = idx >> 5, d = idx & 31;
        float mx = -FLT_MAX;
        #pragma unroll
        for (int k = 0; k < KNNK; k++) mx = fmaxf(mx, sKK[p][k * DIMK + d]);
        float sum = 0.f;
        #pragma unroll
        for (int k = 0; k < KNNK; k++) {
            const float e = expf(sKK[p][k * DIMK + d] - mx);
            sKK[p][k * DIMK + d] = e;
            sum += e;
        }
        const float inv = 1.f / sum;
        #pragma unroll
        for (int k = 0; k < KNNK; k++) sKK[p][k * DIMK + d] *= inv;
    }
    __syncthreads();

    // ---- kv[p][d][v] = sum_k kk[k][d] * v[k][v] -------------------------------------
    for (int i = t; i < 2 * DIMK * DIMV; i += 128) {
        const int p = i >> 9;
        const int r = i & 511;
        const int d = r >> 4, vd = r & 15;
        float acc = 0.f;
        #pragma unroll
        for (int k = 0; k < KNNK; k++)
            acc += sKK[p][k * DIMK + d] * sV[p][k * DIMV + vd];
        sKV[p][r] = acc;
    }
    __syncthreads();

    // ---- out = LN_128(q @ kv) both points, write transposed ----------------------------
    {
        const int h = t >> 4, vd = t & 15;
        float acc0 = 0.f, acc1 = 0.f;
        #pragma unroll
        for (int d = 0; d < DIMK; d++) {
            acc0 += sQ[0][h * DIMK + d] * sKV[0][d * DIMV + vd];
            acc1 += sQ[1][h * DIMK + d] * sKV[1][d * DIMV + vd];
        }
        const float4 ssq = block_sum4_128(
            make_float4(acc0, acc0 * acc0, acc1, acc1 * acc1), sred, sbc);
        const float m0 = ssq.x * (1.f / COUT);
        const float i0 = rsqrtf(ssq.y * (1.f / COUT) - m0 * m0 + EPSF);
        const float m1 = ssq.z * (1.f / COUT);
        const float i1 = rsqrtf(ssq.w * (1.f / COUT) - m1 * m1 + EPSF);
        const float lw = lnow[t], lb = lnob[t];
        float* op = out + XYZ_TOT + ((size_t)b * COUT + t) * NN + n0;
        op[0] = (acc0 - m0) * i0 * lw + lb;
        op[1] = (acc1 - m1) * i1 * lw + lb;
    }
}

// ---------------------------------------------------------------------------
// launch
// ---------------------------------------------------------------------------
extern "C" void kernel_launch(void* const* d_in, const int* in_sizes, int n_in,
                              void* d_out, int out_size)
{
    const float* x    = (const float*)d_in[0];
    const float* Wh   = (const float*)d_in[1];
    const float* W1   = (const float*)d_in[2];
    const float* g1   = (const float*)d_in[3];
    const float* b1   = (const float*)d_in[4];
    const float* W2   = (const float*)d_in[5];
    const float* g2   = (const float*)d_in[6];
    const float* b2   = (const float*)d_in[7];
    const float* Wq   = (const float*)d_in[8];
    const float* lnqw = (const float*)d_in[9];
    const float* lnqb = (const float*)d_in[10];
    const float* Wv   = (const float*)d_in[11];
    const float* lnvw = (const float*)d_in[12];
    const float* lnvb = (const float*)d_in[13];
    const float* Wk   = (const float*)d_in[14];
    const float* lnow = (const float*)d_in[15];
    const float* lnob = (const float*)d_in[16];
    float* out = (float*)d_out;

    const int pack_total = (CR/4)*CH + (CFE/4)*CH + (CH/4)*CH + (CH/4)*NHEAD*DIMK
                         + (CR/4)*DIMV + (CFE/4)*DIMV + (CR/4)*DIMK;
    pack_weights<<<(pack_total + 127) / 128, 128>>>(W1, W2, Wq, Wv, Wk);

    precompute_points<<<BB * NN, 128>>>(x);

    const int knn_smem = (4 * NN + 8 * NN) * (int)sizeof(float);  // 96 KB
    cudaFuncSetAttribute(knn_kernel,
                         cudaFuncAttributeMaxDynamicSharedMemorySize, knn_smem);
    knn_kernel<<<BB * (NN / 8), 256, knn_smem>>>();

    fused_kernel<<<BB * NN / 2, 128>>>(Wh,
                                       g1, b1, g2, b2,
                                       lnqw, lnqb, lnvw, lnvb,
                                       lnow, lnob,
                                       out);
}